// round 6
// baseline (speedup 1.0000x reference)
#include <cuda_runtime.h>
#include <cuda_fp16.h>

#define C 128
#define MAX_USERS   50000
#define MAX_ENT     50000
#define MAX_NODES  100000
#define MAX_E     1000000
#define DEGS 100000          // deg segment stride
#define OFFS 100008          // off/cursor segment stride
#define PS   132             // partials segment stride

// ---------------- scratch (allocation-free: __device__ globals) ----------------
__device__ __half g_hNodeA [(size_t)MAX_NODES * C];
__device__ __half g_hNodeB [(size_t)MAX_NODES * C];
__device__ __half g_hEntB  [(size_t)MAX_ENT   * C];
__device__ __half g_hEntM  [(size_t)MAX_ENT   * C];
__device__ __half g_hQ     [(size_t)MAX_NODES * C];   // reused as hop-2 entity mean after attn
__device__ __half g_hK     [(size_t)MAX_NODES * C];
__device__ __half g_WT     [2 * C * C];               // [mat][n][k] fp16 (W transposed)
__device__ int    g_srt_ent[MAX_E];
__device__ int    g_srt_x  [MAX_E];
__device__ int2   g_srt_i  [MAX_E];
__device__ float2 g_exps   [MAX_E];
__device__ float  g_aug    [MAX_E];
__device__ int    g_deg3   [3 * DEGS];
__device__ int    g_off3   [3 * OFFS];
__device__ int    g_cur3   [3 * OFFS];
__device__ int    g_part3  [3 * PS];

// ---------------- half pack/unpack ----------------
__device__ __forceinline__ uint2 pack4(float a, float b, float c, float d) {
    __half2 h0 = __floats2half2_rn(a, b);
    __half2 h1 = __floats2half2_rn(c, d);
    uint2 r; r.x = *(unsigned*)&h0; r.y = *(unsigned*)&h1; return r;
}
__device__ __forceinline__ float4 unpack4(uint2 v) {
    __half2 h0 = *(__half2*)&v.x, h1 = *(__half2*)&v.y;
    float2 f0 = __half22float2(h0), f1 = __half22float2(h1);
    return make_float4(f0.x, f0.y, f1.x, f1.y);
}

// ================= fp32 (user|ent) -> fp16 concat =================
__global__ __launch_bounds__(256) void conv2(const float* __restrict__ a,
                                             const float* __restrict__ b,
                                             size_t n4a, size_t n4, __half* __restrict__ dst)
{
    size_t i = (size_t)blockIdx.x * 256 + threadIdx.x;
    if (i >= n4) return;
    float4 v = (i < n4a) ? __ldg((const float4*)a + i) : __ldg((const float4*)b + (i - n4a));
    ((uint2*)dst)[i] = pack4(v.x, v.y, v.z, v.w);
}

// ================= W fp32 [k][n] -> fp16 transposed [mat][n][k] =================
__global__ __launch_bounds__(256) void wt_conv(const float* __restrict__ WQ,
                                               const float* __restrict__ WK,
                                               __half* __restrict__ WT)
{
    int i = blockIdx.x * 256 + threadIdx.x;
    if (i >= 2 * C * C) return;
    int mat = i >> 14, r = i & 16383;
    int k = r >> 7, n = r & 127;
    float v = mat ? __ldg(WK + r) : __ldg(WQ + r);
    WT[mat * C * C + n * C + k] = __float2half_rn(v);
}

// ================= CSR build (batched over the 3 graphs) =================
__global__ __launch_bounds__(256) void hist3(
    const int* __restrict__ h_e, int E1,
    const int* __restrict__ h_x, int E2,
    const int* __restrict__ h_u, int E3, int* __restrict__ deg3)
{
    int i = blockIdx.x * 256 + threadIdx.x;
    if (i < E1) { atomicAdd(deg3 + __ldg(h_e + i), 1); return; }
    i -= E1;
    if (i < E2) { atomicAdd(deg3 + DEGS + __ldg(h_x + i), 1); return; }
    i -= E2;
    if (i < E3) atomicAdd(deg3 + 2 * DEGS + __ldg(h_u + i), 1);
}

__global__ __launch_bounds__(1024) void scan_block3(const int* __restrict__ deg3,
                                                    int* __restrict__ off3, int* __restrict__ part3,
                                                    int n0, int n1, int n2)
{
    __shared__ int ws[32];
    int y = blockIdx.y;
    int n = (y == 0) ? n0 : ((y == 1) ? n1 : n2);
    const int* deg = deg3 + y * DEGS;
    int* off = off3 + y * OFFS;
    int* part = part3 + y * PS;
    int t = threadIdx.x;
    int gid = blockIdx.x * 1024 + t;
    int v = (gid < n) ? deg[gid] : 0;
    int x = v;
#pragma unroll
    for (int d = 1; d < 32; d <<= 1) {
        int yv = __shfl_up_sync(0xffffffffu, x, d);
        if ((t & 31) >= d) x += yv;
    }
    if ((t & 31) == 31) ws[t >> 5] = x;
    __syncthreads();
    if (t < 32) {
        int s = ws[t];
#pragma unroll
        for (int d = 1; d < 32; d <<= 1) {
            int yv = __shfl_up_sync(0xffffffffu, s, d);
            if (t >= d) s += yv;
        }
        ws[t] = s;
    }
    __syncthreads();
    int excl = x - v + ((t >= 32) ? ws[(t >> 5) - 1] : 0);
    if (gid < n) off[gid] = excl;
    if (t == 1023) part[blockIdx.x] = excl + v;
}

__global__ void scan_part3(int* __restrict__ part3)
{
    int t = threadIdx.x;            // 96 threads
    int w = t >> 5, lane = t & 31;
    int* part = part3 + w * PS;
    int v[4];
#pragma unroll
    for (int i = 0; i < 4; i++) v[i] = part[lane * 4 + i];
    int loc = v[0] + v[1] + v[2] + v[3];
    int x = loc;
#pragma unroll
    for (int d = 1; d < 32; d <<= 1) {
        int y = __shfl_up_sync(0xffffffffu, x, d);
        if (lane >= d) x += y;
    }
    int excl = x - loc;
#pragma unroll
    for (int i = 0; i < 4; i++) { part[lane * 4 + i] = excl; excl += v[i]; }
}

__global__ __launch_bounds__(256) void add_offs3(int* __restrict__ off3,
                                                 const int* __restrict__ part3,
                                                 int n0, int n1, int n2)
{
    int y = blockIdx.y;
    int n = (y == 0) ? n0 : ((y == 1) ? n1 : n2);
    int* off = off3 + y * OFFS;
    const int* part = part3 + y * PS;
    int i = blockIdx.x * 256 + threadIdx.x;
    if (i < n) off[i] += part[i >> 10];
    else if (i == n) off[i] = part[(n + 1023) >> 10];
}

__global__ __launch_bounds__(256) void scat3(
    const int* __restrict__ eh, const int* __restrict__ et, const int* __restrict__ ety, int E1,
    const int* __restrict__ xh, const int* __restrict__ xt, int E2,
    const int* __restrict__ ir, const int* __restrict__ ic, const float* __restrict__ iv, int E3,
    int* __restrict__ cur3, int* __restrict__ srt_e, int* __restrict__ srt_x, int2* __restrict__ srt_i)
{
    int i = blockIdx.x * 256 + threadIdx.x;
    if (i < E1) {
        int p = atomicAdd(cur3 + __ldg(eh + i), 1);
        srt_e[p] = __ldg(et + i) | ((__ldg(ety + i) - 1) << 16);
        return;
    }
    i -= E1;
    if (i < E2) {
        int p = atomicAdd(cur3 + OFFS + __ldg(xh + i), 1);
        srt_x[p] = __ldg(xt + i);
        return;
    }
    i -= E2;
    if (i < E3) {
        int p = atomicAdd(cur3 + 2 * OFFS + __ldg(ir + i), 1);
        srt_i[p] = make_int2(__ldg(ic + i), __float_as_int(__ldg(iv + i)));
    }
}

// ================= Q/K projection via HMMA =================
#define SB_H (2 * 128 * 136)
#define SA_H (64 * 136)
__global__ __launch_bounds__(256) void qk_mma(
    const __half* __restrict__ node, const __half* __restrict__ WT,
    __half* __restrict__ Q, __half* __restrict__ K, int n)
{
    extern __shared__ __half sh[];
    __half* sB = sh;            // [mat*128 + n][136]
    __half* sA = sh + SB_H;     // [row][136]
    int t = threadIdx.x;
    int row0 = blockIdx.x * 64;

    for (int i = t; i < 4096; i += 256) {
        uint4 v = __ldg((const uint4*)WT + i);
        int nn = i >> 4, k8 = (i & 15) << 3;
        *(uint4*)(sB + nn * 136 + k8) = v;
    }
    for (int i = t; i < 1024; i += 256) {
        int r = i >> 4, k8 = (i & 15) << 3;
        int gr = row0 + r;
        uint4 v = make_uint4(0u, 0u, 0u, 0u);
        if (gr < n) v = __ldg((const uint4*)(node + (size_t)gr * C) + (i & 15));
        *(uint4*)(sA + r * 136 + k8) = v;
    }
    __syncthreads();

    int lane = t & 31, wid = t >> 5;
    int rg = wid & 3, cg = wid >> 2;
    int arow = rg * 16 + (lane >> 2);
    int kq = (lane & 3) * 2;

#pragma unroll
    for (int mat = 0; mat < 2; mat++) {
        float acc[8][4];
#pragma unroll
        for (int nt = 0; nt < 8; nt++)
#pragma unroll
            for (int c = 0; c < 4; c++) acc[nt][c] = 0.f;

#pragma unroll
        for (int kk = 0; kk < 128; kk += 16) {
            unsigned a0 = *(unsigned*)(sA + arow * 136 + kk + kq);
            unsigned a1 = *(unsigned*)(sA + (arow + 8) * 136 + kk + kq);
            unsigned a2 = *(unsigned*)(sA + arow * 136 + kk + kq + 8);
            unsigned a3 = *(unsigned*)(sA + (arow + 8) * 136 + kk + kq + 8);
#pragma unroll
            for (int nt = 0; nt < 8; nt++) {
                int nn = mat * 128 + cg * 64 + nt * 8 + (lane >> 2);
                unsigned b0 = *(unsigned*)(sB + nn * 136 + kk + kq);
                unsigned b1 = *(unsigned*)(sB + nn * 136 + kk + kq + 8);
                asm volatile(
                    "mma.sync.aligned.m16n8k16.row.col.f32.f16.f16.f32 "
                    "{%0,%1,%2,%3}, {%4,%5,%6,%7}, {%8,%9}, {%0,%1,%2,%3};"
                    : "+f"(acc[nt][0]), "+f"(acc[nt][1]), "+f"(acc[nt][2]), "+f"(acc[nt][3])
                    : "r"(a0), "r"(a1), "r"(a2), "r"(a3), "r"(b0), "r"(b1));
            }
        }

        __half* outb = mat ? K : Q;
        int grow = row0 + rg * 16 + (lane >> 2);
#pragma unroll
        for (int nt = 0; nt < 8; nt++) {
            int col = cg * 64 + nt * 8 + (lane & 3) * 2;
            if (grow < n) {
                __half2 h = __floats2half2_rn(acc[nt][0], acc[nt][1]);
                *(__half2*)(outb + (size_t)grow * C + col) = h;
            }
            if (grow + 8 < n) {
                __half2 h = __floats2half2_rn(acc[nt][2], acc[nt][3]);
                *(__half2*)(outb + (size_t)(grow + 8) * C + col) = h;
            }
        }
    }
}

// ================= device bodies (R4 gather structure) =================
__device__ __forceinline__ void attn_body(
    int gw, int lane, const int* __restrict__ off, const int* __restrict__ srt,
    const __half* __restrict__ Q, const __half* __restrict__ K,
    float2* __restrict__ exps, float* __restrict__ aug)
{
    int base = off[gw], end = off[gw + 1];
    if (base == end) return;
    float4 q = unpack4(__ldg((const uint2*)(Q + (size_t)gw * C) + lane));
    float z0 = 0.f, z1 = 0.f;
    for (int e0 = base; e0 < end; e0 += 32) {
        int cnt = min(32, end - e0);
        int meta = (lane < cnt) ? __ldg(srt + e0 + lane) : 0;
        float my0 = 0.f, my1 = 0.f;
        for (int j = 0; j < cnt; j++) {
            int tl = __shfl_sync(0xffffffffu, meta, j);
            float4 k4 = unpack4(__ldg((const uint2*)(K + (size_t)tl * C) + lane));
            float p = q.x * k4.x + q.y * k4.y + q.z * k4.z + q.w * k4.w;
            p += __shfl_xor_sync(0xffffffffu, p, 8);
            p += __shfl_xor_sync(0xffffffffu, p, 4);
            p += __shfl_xor_sync(0xffffffffu, p, 2);
            p += __shfl_xor_sync(0xffffffffu, p, 1);
            float po = __shfl_xor_sync(0xffffffffu, p, 16);
            float s0 = (lane < 16) ? p : po;
            float s1 = (lane < 16) ? po : p;
            float ex0 = __expf(s0 * 0.125f);
            float ex1 = __expf(s1 * 0.125f);
            z0 += ex0; z1 += ex1;
            if (lane == j) { my0 = ex0; my1 = ex1; }
        }
        if (lane < cnt) exps[e0 + lane] = make_float2(my0, my1);
    }
    float iz0 = 0.5f / z0, iz1 = 0.5f / z1;
    for (int e0 = base; e0 < end; e0 += 32) {
        int cnt = min(32, end - e0);
        if (lane < cnt) {
            float2 ex = exps[e0 + lane];
            aug[e0 + lane] = ex.x * iz0 + ex.y * iz1;
        }
    }
}

__device__ __forceinline__ void ent_body(
    int gw, int lane, const int* __restrict__ off, const int* __restrict__ srt,
    const __half* __restrict__ src, const float* sW,
    __half* __restrict__ mean_out, __half* __restrict__ cur_out,
    float* __restrict__ res, const float* __restrict__ res_init)
{
    int base = off[gw], end = off[gw + 1];
    float4 acc = make_float4(0.f, 0.f, 0.f, 0.f);
    for (int e0 = base; e0 < end; e0 += 32) {
        int cnt = min(32, end - e0);
        int meta = (lane < cnt) ? __ldg(srt + e0 + lane) : 0;
        int j = 0;
        for (; j + 4 <= cnt; j += 4) {
            int m0 = __shfl_sync(0xffffffffu, meta, j + 0);
            int m1 = __shfl_sync(0xffffffffu, meta, j + 1);
            int m2 = __shfl_sync(0xffffffffu, meta, j + 2);
            int m3 = __shfl_sync(0xffffffffu, meta, j + 3);
            float4 v0 = unpack4(__ldg((const uint2*)(src + (size_t)(m0 & 0xFFFF) * C) + lane));
            float4 v1 = unpack4(__ldg((const uint2*)(src + (size_t)(m1 & 0xFFFF) * C) + lane));
            float4 v2 = unpack4(__ldg((const uint2*)(src + (size_t)(m2 & 0xFFFF) * C) + lane));
            float4 v3 = unpack4(__ldg((const uint2*)(src + (size_t)(m3 & 0xFFFF) * C) + lane));
            float4 w0 = *((const float4*)(sW + (((unsigned)m0) >> 16) * C) + lane);
            float4 w1 = *((const float4*)(sW + (((unsigned)m1) >> 16) * C) + lane);
            float4 w2 = *((const float4*)(sW + (((unsigned)m2) >> 16) * C) + lane);
            float4 w3 = *((const float4*)(sW + (((unsigned)m3) >> 16) * C) + lane);
            acc.x += v0.x * w0.x + v1.x * w1.x + v2.x * w2.x + v3.x * w3.x;
            acc.y += v0.y * w0.y + v1.y * w1.y + v2.y * w2.y + v3.y * w3.y;
            acc.z += v0.z * w0.z + v1.z * w1.z + v2.z * w2.z + v3.z * w3.z;
            acc.w += v0.w * w0.w + v1.w * w1.w + v2.w * w2.w + v3.w * w3.w;
        }
        for (; j < cnt; j++) {
            int m0 = __shfl_sync(0xffffffffu, meta, j);
            float4 v0 = unpack4(__ldg((const uint2*)(src + (size_t)(m0 & 0xFFFF) * C) + lane));
            float4 w0 = *((const float4*)(sW + (((unsigned)m0) >> 16) * C) + lane);
            acc.x += v0.x * w0.x; acc.y += v0.y * w0.y;
            acc.z += v0.z * w0.z; acc.w += v0.w * w0.w;
        }
    }
    float inv = 1.0f / fmaxf((float)(end - base), 1.0f);
    float4 m = make_float4(acc.x * inv, acc.y * inv, acc.z * inv, acc.w * inv);
    ((uint2*)(mean_out + (size_t)gw * C))[lane] = pack4(m.x, m.y, m.z, m.w);
    float ss = m.x * m.x + m.y * m.y + m.z * m.z + m.w * m.w;
    ss += __shfl_xor_sync(0xffffffffu, ss, 16);
    ss += __shfl_xor_sync(0xffffffffu, ss, 8);
    ss += __shfl_xor_sync(0xffffffffu, ss, 4);
    ss += __shfl_xor_sync(0xffffffffu, ss, 2);
    ss += __shfl_xor_sync(0xffffffffu, ss, 1);
    float ni = 1.0f / fmaxf(sqrtf(ss), 1e-12f);
    float4 o = make_float4(m.x * ni, m.y * ni, m.z * ni, m.w * ni);
    if (cur_out) ((uint2*)(cur_out + (size_t)gw * C))[lane] = pack4(o.x, o.y, o.z, o.w);
    float4 r = __ldg((const float4*)(res_init + (size_t)gw * C) + lane);
    r.x += o.x; r.y += o.y; r.z += o.z; r.w += o.w;
    ((float4*)(res + (size_t)gw * C))[lane] = r;
}

__device__ __forceinline__ void node_body(
    int gw, int lane, const int* __restrict__ off, const int* __restrict__ srt,
    const float* __restrict__ aug, const __half* __restrict__ src,
    __half* __restrict__ cur_out, float* __restrict__ res,
    const float* __restrict__ ri0, const float* __restrict__ ri1, int split)
{
    int base = off[gw], end = off[gw + 1];
    float4 acc = make_float4(0.f, 0.f, 0.f, 0.f);
    for (int e0 = base; e0 < end; e0 += 32) {
        int cnt = min(32, end - e0);
        int meta = 0; float av = 0.f;
        if (lane < cnt) { meta = __ldg(srt + e0 + lane); av = __ldg(aug + e0 + lane); }
        int j = 0;
        for (; j + 4 <= cnt; j += 4) {
            int m0 = __shfl_sync(0xffffffffu, meta, j + 0);
            int m1 = __shfl_sync(0xffffffffu, meta, j + 1);
            int m2 = __shfl_sync(0xffffffffu, meta, j + 2);
            int m3 = __shfl_sync(0xffffffffu, meta, j + 3);
            float a0 = __shfl_sync(0xffffffffu, av, j + 0);
            float a1 = __shfl_sync(0xffffffffu, av, j + 1);
            float a2 = __shfl_sync(0xffffffffu, av, j + 2);
            float a3 = __shfl_sync(0xffffffffu, av, j + 3);
            float4 v0 = unpack4(__ldg((const uint2*)(src + (size_t)m0 * C) + lane));
            float4 v1 = unpack4(__ldg((const uint2*)(src + (size_t)m1 * C) + lane));
            float4 v2 = unpack4(__ldg((const uint2*)(src + (size_t)m2 * C) + lane));
            float4 v3 = unpack4(__ldg((const uint2*)(src + (size_t)m3 * C) + lane));
            acc.x += v0.x * a0 + v1.x * a1 + v2.x * a2 + v3.x * a3;
            acc.y += v0.y * a0 + v1.y * a1 + v2.y * a2 + v3.y * a3;
            acc.z += v0.z * a0 + v1.z * a1 + v2.z * a2 + v3.z * a3;
            acc.w += v0.w * a0 + v1.w * a1 + v2.w * a2 + v3.w * a3;
        }
        for (; j < cnt; j++) {
            int m0 = __shfl_sync(0xffffffffu, meta, j);
            float a0 = __shfl_sync(0xffffffffu, av, j);
            float4 v0 = unpack4(__ldg((const uint2*)(src + (size_t)m0 * C) + lane));
            acc.x += v0.x * a0; acc.y += v0.y * a0;
            acc.z += v0.z * a0; acc.w += v0.w * a0;
        }
    }
    float ss = acc.x * acc.x + acc.y * acc.y + acc.z * acc.z + acc.w * acc.w;
    ss += __shfl_xor_sync(0xffffffffu, ss, 16);
    ss += __shfl_xor_sync(0xffffffffu, ss, 8);
    ss += __shfl_xor_sync(0xffffffffu, ss, 4);
    ss += __shfl_xor_sync(0xffffffffu, ss, 2);
    ss += __shfl_xor_sync(0xffffffffu, ss, 1);
    float ni = 1.0f / fmaxf(sqrtf(ss), 1e-12f);
    float4 o = make_float4(acc.x * ni, acc.y * ni, acc.z * ni, acc.w * ni);
    if (cur_out) ((uint2*)(cur_out + (size_t)gw * C))[lane] = pack4(o.x, o.y, o.z, o.w);
    const float* rib = (gw < split) ? ri0 + (size_t)gw * C : ri1 + (size_t)(gw - split) * C;
    float4 r = __ldg((const float4*)rib + lane);
    r.x += o.x; r.y += o.y; r.z += o.z; r.w += o.w;
    ((float4*)(res + (size_t)gw * C))[lane] = r;
}

__device__ __forceinline__ void user_body(
    int gw, int lane, const int* __restrict__ off, const int2* __restrict__ srt,
    const __half* __restrict__ src, float* __restrict__ res,
    const float* __restrict__ res_init)
{
    int base = off[gw], end = off[gw + 1];
    float4 acc = make_float4(0.f, 0.f, 0.f, 0.f);
    for (int e0 = base; e0 < end; e0 += 32) {
        int cnt = min(32, end - e0);
        int mc = 0; float mv = 0.f;
        if (lane < cnt) { int2 p = __ldg(srt + e0 + lane); mc = p.x; mv = __int_as_float(p.y); }
        int j = 0;
        for (; j + 4 <= cnt; j += 4) {
            int c0 = __shfl_sync(0xffffffffu, mc, j + 0);
            int c1 = __shfl_sync(0xffffffffu, mc, j + 1);
            int c2 = __shfl_sync(0xffffffffu, mc, j + 2);
            int c3 = __shfl_sync(0xffffffffu, mc, j + 3);
            float a0 = __shfl_sync(0xffffffffu, mv, j + 0);
            float a1 = __shfl_sync(0xffffffffu, mv, j + 1);
            float a2 = __shfl_sync(0xffffffffu, mv, j + 2);
            float a3 = __shfl_sync(0xffffffffu, mv, j + 3);
            float4 v0 = unpack4(__ldg((const uint2*)(src + (size_t)c0 * C) + lane));
            float4 v1 = unpack4(__ldg((const uint2*)(src + (size_t)c1 * C) + lane));
            float4 v2 = unpack4(__ldg((const uint2*)(src + (size_t)c2 * C) + lane));
            float4 v3 = unpack4(__ldg((const uint2*)(src + (size_t)c3 * C) + lane));
            acc.x += v0.x * a0 + v1.x * a1 + v2.x * a2 + v3.x * a3;
            acc.y += v0.y * a0 + v1.y * a1 + v2.y * a2 + v3.y * a3;
            acc.z += v0.z * a0 + v1.z * a1 + v2.z * a2 + v3.z * a3;
            acc.w += v0.w * a0 + v1.w * a1 + v2.w * a2 + v3.w * a3;
        }
        for (; j < cnt; j++) {
            int c0 = __shfl_sync(0xffffffffu, mc, j);
            float a0 = __shfl_sync(0xffffffffu, mv, j);
            float4 v0 = unpack4(__ldg((const uint2*)(src + (size_t)c0 * C) + lane));
            acc.x += v0.x * a0; acc.y += v0.y * a0;
            acc.z += v0.z * a0; acc.w += v0.w * a0;
        }
    }
    float ss = acc.x * acc.x + acc.y * acc.y + acc.z * acc.z + acc.w * acc.w;
    ss += __shfl_xor_sync(0xffffffffu, ss, 16);
    ss += __shfl_xor_sync(0xffffffffu, ss, 8);
    ss += __shfl_xor_sync(0xffffffffu, ss, 4);
    ss += __shfl_xor_sync(0xffffffffu, ss, 2);
    ss += __shfl_xor_sync(0xffffffffu, ss, 1);
    float ni = 1.0f / fmaxf(sqrtf(ss), 1e-12f);
    float4 o = make_float4(acc.x * ni, acc.y * ni, acc.z * ni, acc.w * ni);
    float4 r = __ldg((const float4*)(res_init + (size_t)gw * C) + lane);
    r.x += o.x; r.y += o.y; r.z += o.z; r.w += o.w;
    ((float4*)(res + (size_t)gw * C))[lane] = r;
}

// ================= merged launches (independent passes co-resident) =================
// M1: attention (n_nodes rows)  ∥  hop-1 entity agg (n_ent rows)
__global__ __launch_bounds__(256) void mega1(
    const int* __restrict__ off_n, const int* __restrict__ srt_x,
    const __half* __restrict__ Q, const __half* __restrict__ K,
    float2* __restrict__ exps, float* __restrict__ aug, int n_nodes, int nbA,
    const int* __restrict__ off_e, const int* __restrict__ srt_e,
    const __half* __restrict__ entA, const float* __restrict__ wgt,
    __half* __restrict__ entM1, __half* __restrict__ entB,
    float* __restrict__ ent_res, const float* __restrict__ ent0, int n_ent)
{
    __shared__ float sW[15 * C];
    int lane = threadIdx.x & 31, wid = threadIdx.x >> 5;
    int b = blockIdx.x;
    if (b < nbA) {
        int gw = b * 8 + wid;
        if (gw < n_nodes) attn_body(gw, lane, off_n, srt_x, Q, K, exps, aug);
    } else {
        for (int i = threadIdx.x; i < 15 * C; i += 256) sW[i] = wgt[i];
        __syncthreads();
        int gw = (b - nbA) * 8 + wid;
        if (gw < n_ent)
            ent_body(gw, lane, off_e, srt_e, entA, sW, entM1, entB, ent_res, ent0);
    }
}

// M2: hop-1 node agg  ∥  hop-1 user agg  ∥  hop-2 entity agg
__global__ __launch_bounds__(256) void mega2(
    const int* __restrict__ off_n, const int* __restrict__ srt_x,
    const float* __restrict__ aug, const __half* __restrict__ nodeA,
    __half* __restrict__ nodeB, float* __restrict__ node_res,
    const float* __restrict__ user0, const float* __restrict__ ent0,
    int n_users, int n_nodes, int nbN,
    const int* __restrict__ off_u, const int2* __restrict__ srt_i,
    const __half* __restrict__ entM1, float* __restrict__ user_res, int nbU,
    const int* __restrict__ off_e, const int* __restrict__ srt_e,
    const __half* __restrict__ entB, const float* __restrict__ wgt,
    __half* __restrict__ entM2, float* __restrict__ ent_res, int n_ent)
{
    __shared__ float sW[15 * C];
    int lane = threadIdx.x & 31, wid = threadIdx.x >> 5;
    int b = blockIdx.x;
    if (b < nbN) {
        int gw = b * 8 + wid;
        if (gw < n_nodes)
            node_body(gw, lane, off_n, srt_x, aug, nodeA, nodeB, node_res,
                      user0, ent0, n_users);
    } else if (b < nbN + nbU) {
        int gw = (b - nbN) * 8 + wid;
        if (gw < n_users)
            user_body(gw, lane, off_u, srt_i, entM1, user_res, user0);
    } else {
        for (int i = threadIdx.x; i < 15 * C; i += 256) sW[i] = wgt[i];
        __syncthreads();
        int gw = (b - nbN - nbU) * 8 + wid;
        if (gw < n_ent)
            ent_body(gw, lane, off_e, srt_e, entB, sW, entM2, (__half*)0, ent_res, ent_res);
    }
}

// M3: hop-2 node agg  ∥  hop-2 user agg
__global__ __launch_bounds__(256) void mega3(
    const int* __restrict__ off_n, const int* __restrict__ srt_x,
    const float* __restrict__ aug, const __half* __restrict__ nodeB,
    float* __restrict__ node_res, int n_nodes, int nbN,
    const int* __restrict__ off_u, const int2* __restrict__ srt_i,
    const __half* __restrict__ entM2, float* __restrict__ user_res, int n_users)
{
    int lane = threadIdx.x & 31, wid = threadIdx.x >> 5;
    int b = blockIdx.x;
    if (b < nbN) {
        int gw = b * 8 + wid;
        if (gw < n_nodes)
            node_body(gw, lane, off_n, srt_x, aug, nodeB, (__half*)0, node_res,
                      node_res, node_res, n_nodes);
    } else {
        int gw = (b - nbN) * 8 + wid;
        if (gw < n_users)
            user_body(gw, lane, off_u, srt_i, entM2, user_res, user_res);
    }
}

// ================= host launcher =================
extern "C" void kernel_launch(void* const* d_in, const int* in_sizes, int n_in,
                              void* d_out, int out_size)
{
    const float* user   = (const float*)d_in[0];
    const float* ent    = (const float*)d_in[1];
    const int*   eidx   = (const int*)  d_in[2];
    const int*   etype  = (const int*)  d_in[3];
    const int*   exidx  = (const int*)  d_in[4];
    const int*   irows  = (const int*)  d_in[6];
    const int*   icols  = (const int*)  d_in[7];
    const float* ivals  = (const float*)d_in[8];
    const float* weight = (const float*)d_in[9];
    const float* WQ     = (const float*)d_in[11];
    const float* WK     = (const float*)d_in[12];

    int n_users = in_sizes[0] / C;
    int n_ent   = in_sizes[1] / C;
    int n_nodes = n_users + n_ent;
    int E   = in_sizes[3];
    int EX  = in_sizes[5];
    int NNZ = in_sizes[6];

    size_t UB = (size_t)n_users * C;
    size_t EB = (size_t)n_ent * C;

    float *augp;
    __half *hNodeA, *hNodeB, *hEntB, *hEntM, *hQ, *hK, *WT;
    float2* exps;
    int *srt_e, *srt_x, *off3, *cur3, *deg3, *part3;
    int2* srt_i;
    cudaGetSymbolAddress((void**)&hNodeA, g_hNodeA);
    cudaGetSymbolAddress((void**)&hNodeB, g_hNodeB);
    cudaGetSymbolAddress((void**)&hEntB,  g_hEntB);
    cudaGetSymbolAddress((void**)&hEntM,  g_hEntM);
    cudaGetSymbolAddress((void**)&hQ,     g_hQ);
    cudaGetSymbolAddress((void**)&hK,     g_hK);
    cudaGetSymbolAddress((void**)&WT,     g_WT);
    cudaGetSymbolAddress((void**)&augp,   g_aug);
    cudaGetSymbolAddress((void**)&exps,   g_exps);
    cudaGetSymbolAddress((void**)&srt_e,  g_srt_ent);
    cudaGetSymbolAddress((void**)&srt_x,  g_srt_x);
    cudaGetSymbolAddress((void**)&srt_i,  g_srt_i);
    cudaGetSymbolAddress((void**)&off3,   g_off3);
    cudaGetSymbolAddress((void**)&cur3,   g_cur3);
    cudaGetSymbolAddress((void**)&deg3,   g_deg3);
    cudaGetSymbolAddress((void**)&part3,  g_part3);

    int* off_e = off3;
    int* off_n = off3 + OFFS;
    int* off_u = off3 + 2 * OFFS;

    float* out = (float*)d_out;
    float* user_res = out;              // [n_users, C]
    float* ent_res  = out + UB;         // [n_ent, C]
    float* node_res = out + UB + EB;    // [n_nodes, C]

    const int* eh = eidx;          const int* et = eidx + E;
    const int* xh = exidx;         const int* xt = exidx + EX;

    {
        size_t n4 = (size_t)n_nodes * 32;
        conv2<<<(unsigned)((n4 + 255) / 256), 256>>>(user, ent, UB / 4, n4, hNodeA);
    }
    wt_conv<<<(2 * C * C + 255) / 256, 256>>>(WQ, WK, WT);

    // ---- batched CSR build for the 3 graphs ----
    cudaMemsetAsync(deg3, 0, 3 * DEGS * 4);
    {
        int tot = E + EX + NNZ;
        hist3<<<(tot + 255) / 256, 256>>>(eh, E, xh, EX, irows, NNZ, deg3);
    }
    {
        dim3 g((n_nodes + 1023) >> 10, 3);
        scan_block3<<<g, 1024>>>(deg3, off3, part3, n_ent, n_nodes, n_users);
        scan_part3<<<1, 96>>>(part3);
        dim3 g2((n_nodes + 256) / 256 + 1, 3);
        add_offs3<<<g2, 256>>>(off3, part3, n_ent, n_nodes, n_users);
    }
    cudaMemcpyAsync(cur3, off3, 3 * OFFS * 4, cudaMemcpyDeviceToDevice);
    {
        int tot = E + EX + NNZ;
        scat3<<<(tot + 255) / 256, 256>>>(eh, et, etype, E, xh, xt, EX,
                                          irows, icols, ivals, NNZ,
                                          cur3, srt_e, srt_x, srt_i);
    }

    // ---- Q/K projections ----
    {
        int smem = (SB_H + SA_H) * 2;
        cudaFuncSetAttribute(qk_mma, cudaFuncAttributeMaxDynamicSharedMemorySize, smem);
        qk_mma<<<(n_nodes + 63) / 64, 256, smem>>>(hNodeA, WT, hQ, hK, n_nodes);
    }

    int nbA = (n_nodes + 7) / 8;
    int nbE = (n_ent + 7) / 8;
    int nbN = (n_nodes + 7) / 8;
    int nbU = (n_users + 7) / 8;
    __half* hEntM2 = hQ;   // hQ is dead after mega1's attention

    // M1: attention ∥ hop-1 entity agg
    mega1<<<nbA + nbE, 256>>>(off_n, srt_x, hQ, hK, exps, augp, n_nodes, nbA,
                              off_e, srt_e, hNodeA + UB, weight, hEntM, hEntB,
                              ent_res, ent, n_ent);
    // M2: hop-1 node agg ∥ hop-1 user agg ∥ hop-2 entity agg
    mega2<<<nbN + nbU + nbE, 256>>>(off_n, srt_x, augp, hNodeA, hNodeB, node_res,
                                    user, ent, n_users, n_nodes, nbN,
                                    off_u, srt_i, hEntM, user_res, nbU,
                                    off_e, srt_e, hEntB, weight, hEntM2, ent_res, n_ent);
    // M3: hop-2 node agg ∥ hop-2 user agg
    mega3<<<nbN + nbU, 256>>>(off_n, srt_x, augp, hNodeB, node_res, n_nodes, nbN,
                              off_u, srt_i, hEntM2, user_res, n_users);
}

// round 7
// speedup vs baseline: 1.1593x; 1.1593x over previous
#include <cuda_runtime.h>
#include <cuda_fp16.h>

#define C 128
#define MAX_USERS   50000
#define MAX_ENT     50000
#define MAX_NODES  100000
#define MAX_E     1000000
#define DEGS 100000          // deg segment stride
#define OFFS 100008          // off/cursor segment stride
#define PS   132             // partials segment stride

// ---------------- scratch (allocation-free: __device__ globals) ----------------
__device__ __half g_hNodeA [(size_t)MAX_NODES * C];
__device__ __half g_hNodeB [(size_t)MAX_NODES * C];
__device__ __half g_hEntB  [(size_t)MAX_ENT   * C];
__device__ __half g_hEntM  [(size_t)MAX_ENT   * C];   // hop-1 entity mean
__device__ __half g_hEntM2 [(size_t)MAX_ENT   * C];   // hop-2 entity mean
__device__ __half g_hUserB [(size_t)MAX_USERS * C];   // hop-1 user norm
__device__ __half g_hQ     [(size_t)MAX_NODES * C];
__device__ __half g_hK     [(size_t)MAX_NODES * C];
__device__ __half g_WT     [2 * C * C];               // [mat][n][k] fp16 (W transposed)
__device__ int    g_srt_ent[MAX_E];
__device__ int    g_srt_x  [MAX_E];
__device__ int2   g_srt_i  [MAX_E];
__device__ float2 g_exps   [MAX_E];
__device__ float  g_aug    [MAX_E];
__device__ int    g_deg3   [3 * DEGS];
__device__ int    g_off3   [3 * OFFS];
__device__ int    g_cur3   [3 * OFFS];
__device__ int    g_part3  [3 * PS];

// ---------------- streams/events (host objects, created once pre-checkpoint) ----
struct HxStreams {
    cudaStream_t sA, sB;
    cudaEvent_t evFork, evE1, evA, evB;
    HxStreams() {
        cudaStreamCreateWithFlags(&sA, cudaStreamNonBlocking);
        cudaStreamCreateWithFlags(&sB, cudaStreamNonBlocking);
        cudaEventCreateWithFlags(&evFork, cudaEventDisableTiming);
        cudaEventCreateWithFlags(&evE1,   cudaEventDisableTiming);
        cudaEventCreateWithFlags(&evA,    cudaEventDisableTiming);
        cudaEventCreateWithFlags(&evB,    cudaEventDisableTiming);
    }
};
static HxStreams g_hx;

// ---------------- half pack/unpack ----------------
__device__ __forceinline__ uint2 pack4(float a, float b, float c, float d) {
    __half2 h0 = __floats2half2_rn(a, b);
    __half2 h1 = __floats2half2_rn(c, d);
    uint2 r; r.x = *(unsigned*)&h0; r.y = *(unsigned*)&h1; return r;
}
__device__ __forceinline__ float4 unpack4(uint2 v) {
    __half2 h0 = *(__half2*)&v.x, h1 = *(__half2*)&v.y;
    float2 f0 = __half22float2(h0), f1 = __half22float2(h1);
    return make_float4(f0.x, f0.y, f1.x, f1.y);
}

// ================= fp32 (user|ent) -> fp16 concat =================
__global__ __launch_bounds__(256) void conv2(const float* __restrict__ a,
                                             const float* __restrict__ b,
                                             size_t n4a, size_t n4, __half* __restrict__ dst)
{
    size_t i = (size_t)blockIdx.x * 256 + threadIdx.x;
    if (i >= n4) return;
    float4 v = (i < n4a) ? __ldg((const float4*)a + i) : __ldg((const float4*)b + (i - n4a));
    ((uint2*)dst)[i] = pack4(v.x, v.y, v.z, v.w);
}

// ================= W fp32 [k][n] -> fp16 transposed [mat][n][k] =================
__global__ __launch_bounds__(256) void wt_conv(const float* __restrict__ WQ,
                                               const float* __restrict__ WK,
                                               __half* __restrict__ WT)
{
    int i = blockIdx.x * 256 + threadIdx.x;
    if (i >= 2 * C * C) return;
    int mat = i >> 14, r = i & 16383;
    int k = r >> 7, n = r & 127;
    float v = mat ? __ldg(WK + r) : __ldg(WQ + r);
    WT[mat * C * C + n * C + k] = __float2half_rn(v);
}

// ================= CSR build (batched over the 3 graphs) =================
__global__ __launch_bounds__(256) void hist3(
    const int* __restrict__ h_e, int E1,
    const int* __restrict__ h_x, int E2,
    const int* __restrict__ h_u, int E3, int* __restrict__ deg3)
{
    int i = blockIdx.x * 256 + threadIdx.x;
    if (i < E1) { atomicAdd(deg3 + __ldg(h_e + i), 1); return; }
    i -= E1;
    if (i < E2) { atomicAdd(deg3 + DEGS + __ldg(h_x + i), 1); return; }
    i -= E2;
    if (i < E3) atomicAdd(deg3 + 2 * DEGS + __ldg(h_u + i), 1);
}

__global__ __launch_bounds__(1024) void scan_block3(const int* __restrict__ deg3,
                                                    int* __restrict__ off3, int* __restrict__ part3,
                                                    int n0, int n1, int n2)
{
    __shared__ int ws[32];
    int y = blockIdx.y;
    int n = (y == 0) ? n0 : ((y == 1) ? n1 : n2);
    const int* deg = deg3 + y * DEGS;
    int* off = off3 + y * OFFS;
    int* part = part3 + y * PS;
    int t = threadIdx.x;
    int gid = blockIdx.x * 1024 + t;
    int v = (gid < n) ? deg[gid] : 0;
    int x = v;
#pragma unroll
    for (int d = 1; d < 32; d <<= 1) {
        int yv = __shfl_up_sync(0xffffffffu, x, d);
        if ((t & 31) >= d) x += yv;
    }
    if ((t & 31) == 31) ws[t >> 5] = x;
    __syncthreads();
    if (t < 32) {
        int s = ws[t];
#pragma unroll
        for (int d = 1; d < 32; d <<= 1) {
            int yv = __shfl_up_sync(0xffffffffu, s, d);
            if (t >= d) s += yv;
        }
        ws[t] = s;
    }
    __syncthreads();
    int excl = x - v + ((t >= 32) ? ws[(t >> 5) - 1] : 0);
    if (gid < n) off[gid] = excl;
    if (t == 1023) part[blockIdx.x] = excl + v;
}

__global__ void scan_part3(int* __restrict__ part3)
{
    int t = threadIdx.x;            // 96 threads
    int w = t >> 5, lane = t & 31;
    int* part = part3 + w * PS;
    int v[4];
#pragma unroll
    for (int i = 0; i < 4; i++) v[i] = part[lane * 4 + i];
    int loc = v[0] + v[1] + v[2] + v[3];
    int x = loc;
#pragma unroll
    for (int d = 1; d < 32; d <<= 1) {
        int y = __shfl_up_sync(0xffffffffu, x, d);
        if (lane >= d) x += y;
    }
    int excl = x - loc;
#pragma unroll
    for (int i = 0; i < 4; i++) { part[lane * 4 + i] = excl; excl += v[i]; }
}

__global__ __launch_bounds__(256) void add_offs3(int* __restrict__ off3,
                                                 const int* __restrict__ part3,
                                                 int n0, int n1, int n2)
{
    int y = blockIdx.y;
    int n = (y == 0) ? n0 : ((y == 1) ? n1 : n2);
    int* off = off3 + y * OFFS;
    const int* part = part3 + y * PS;
    int i = blockIdx.x * 256 + threadIdx.x;
    if (i < n) off[i] += part[i >> 10];
    else if (i == n) off[i] = part[(n + 1023) >> 10];
}

__global__ __launch_bounds__(256) void scat3(
    const int* __restrict__ eh, const int* __restrict__ et, const int* __restrict__ ety, int E1,
    const int* __restrict__ xh, const int* __restrict__ xt, int E2,
    const int* __restrict__ ir, const int* __restrict__ ic, const float* __restrict__ iv, int E3,
    int* __restrict__ cur3, int* __restrict__ srt_e, int* __restrict__ srt_x, int2* __restrict__ srt_i)
{
    int i = blockIdx.x * 256 + threadIdx.x;
    if (i < E1) {
        int p = atomicAdd(cur3 + __ldg(eh + i), 1);
        srt_e[p] = __ldg(et + i) | ((__ldg(ety + i) - 1) << 16);
        return;
    }
    i -= E1;
    if (i < E2) {
        int p = atomicAdd(cur3 + OFFS + __ldg(xh + i), 1);
        srt_x[p] = __ldg(xt + i);
        return;
    }
    i -= E2;
    if (i < E3) {
        int p = atomicAdd(cur3 + 2 * OFFS + __ldg(ir + i), 1);
        srt_i[p] = make_int2(__ldg(ic + i), __float_as_int(__ldg(iv + i)));
    }
}

// ================= Q/K projection via HMMA =================
#define SB_H (2 * 128 * 136)
#define SA_H (64 * 136)
__global__ __launch_bounds__(256) void qk_mma(
    const __half* __restrict__ node, const __half* __restrict__ WT,
    __half* __restrict__ Q, __half* __restrict__ K, int n)
{
    extern __shared__ __half sh[];
    __half* sB = sh;            // [mat*128 + n][136]
    __half* sA = sh + SB_H;     // [row][136]
    int t = threadIdx.x;
    int row0 = blockIdx.x * 64;

    for (int i = t; i < 4096; i += 256) {
        uint4 v = __ldg((const uint4*)WT + i);
        int nn = i >> 4, k8 = (i & 15) << 3;
        *(uint4*)(sB + nn * 136 + k8) = v;
    }
    for (int i = t; i < 1024; i += 256) {
        int r = i >> 4, k8 = (i & 15) << 3;
        int gr = row0 + r;
        uint4 v = make_uint4(0u, 0u, 0u, 0u);
        if (gr < n) v = __ldg((const uint4*)(node + (size_t)gr * C) + (i & 15));
        *(uint4*)(sA + r * 136 + k8) = v;
    }
    __syncthreads();

    int lane = t & 31, wid = t >> 5;
    int rg = wid & 3, cg = wid >> 2;
    int arow = rg * 16 + (lane >> 2);
    int kq = (lane & 3) * 2;

#pragma unroll
    for (int mat = 0; mat < 2; mat++) {
        float acc[8][4];
#pragma unroll
        for (int nt = 0; nt < 8; nt++)
#pragma unroll
            for (int c = 0; c < 4; c++) acc[nt][c] = 0.f;

#pragma unroll
        for (int kk = 0; kk < 128; kk += 16) {
            unsigned a0 = *(unsigned*)(sA + arow * 136 + kk + kq);
            unsigned a1 = *(unsigned*)(sA + (arow + 8) * 136 + kk + kq);
            unsigned a2 = *(unsigned*)(sA + arow * 136 + kk + kq + 8);
            unsigned a3 = *(unsigned*)(sA + (arow + 8) * 136 + kk + kq + 8);
#pragma unroll
            for (int nt = 0; nt < 8; nt++) {
                int nn = mat * 128 + cg * 64 + nt * 8 + (lane >> 2);
                unsigned b0 = *(unsigned*)(sB + nn * 136 + kk + kq);
                unsigned b1 = *(unsigned*)(sB + nn * 136 + kk + kq + 8);
                asm volatile(
                    "mma.sync.aligned.m16n8k16.row.col.f32.f16.f16.f32 "
                    "{%0,%1,%2,%3}, {%4,%5,%6,%7}, {%8,%9}, {%0,%1,%2,%3};"
                    : "+f"(acc[nt][0]), "+f"(acc[nt][1]), "+f"(acc[nt][2]), "+f"(acc[nt][3])
                    : "r"(a0), "r"(a1), "r"(a2), "r"(a3), "r"(b0), "r"(b1));
            }
        }

        __half* outb = mat ? K : Q;
        int grow = row0 + rg * 16 + (lane >> 2);
#pragma unroll
        for (int nt = 0; nt < 8; nt++) {
            int col = cg * 64 + nt * 8 + (lane & 3) * 2;
            if (grow < n) {
                __half2 h = __floats2half2_rn(acc[nt][0], acc[nt][1]);
                *(__half2*)(outb + (size_t)grow * C + col) = h;
            }
            if (grow + 8 < n) {
                __half2 h = __floats2half2_rn(acc[nt][2], acc[nt][3]);
                *(__half2*)(outb + (size_t)(grow + 8) * C + col) = h;
            }
        }
    }
}

// ================= fused attention (CSR, R4 structure) =================
__global__ __launch_bounds__(256) void attn_csr(
    const int* __restrict__ off, const int* __restrict__ srt,
    const __half* __restrict__ Q, const __half* __restrict__ K,
    float2* __restrict__ exps, float* __restrict__ aug, int n)
{
    int gw = (blockIdx.x * 256 + threadIdx.x) >> 5, lane = threadIdx.x & 31;
    if (gw >= n) return;
    int base = off[gw], end = off[gw + 1];
    if (base == end) return;
    float4 q = unpack4(__ldg((const uint2*)(Q + (size_t)gw * C) + lane));
    float z0 = 0.f, z1 = 0.f;
    for (int e0 = base; e0 < end; e0 += 32) {
        int cnt = min(32, end - e0);
        int meta = (lane < cnt) ? __ldg(srt + e0 + lane) : 0;
        float my0 = 0.f, my1 = 0.f;
        for (int j = 0; j < cnt; j++) {
            int tl = __shfl_sync(0xffffffffu, meta, j);
            float4 k4 = unpack4(__ldg((const uint2*)(K + (size_t)tl * C) + lane));
            float p = q.x * k4.x + q.y * k4.y + q.z * k4.z + q.w * k4.w;
            p += __shfl_xor_sync(0xffffffffu, p, 8);
            p += __shfl_xor_sync(0xffffffffu, p, 4);
            p += __shfl_xor_sync(0xffffffffu, p, 2);
            p += __shfl_xor_sync(0xffffffffu, p, 1);
            float po = __shfl_xor_sync(0xffffffffu, p, 16);
            float s0 = (lane < 16) ? p : po;
            float s1 = (lane < 16) ? po : p;
            float ex0 = __expf(s0 * 0.125f);
            float ex1 = __expf(s1 * 0.125f);
            z0 += ex0; z1 += ex1;
            if (lane == j) { my0 = ex0; my1 = ex1; }
        }
        if (lane < cnt) exps[e0 + lane] = make_float2(my0, my1);
    }
    float iz0 = 0.5f / z0, iz1 = 0.5f / z1;
    for (int e0 = base; e0 < end; e0 += 32) {
        int cnt = min(32, end - e0);
        if (lane < cnt) {
            float2 ex = exps[e0 + lane];
            aug[e0 + lane] = ex.x * iz0 + ex.y * iz1;
        }
    }
}

// ================= entity KG aggregation (R4 gather; hop1: store fp16, hop2: res) ====
__global__ __launch_bounds__(256) void ent_agg_csr(
    const int* __restrict__ off, const int* __restrict__ srt,
    const __half* __restrict__ src, const float* __restrict__ wgt,
    __half* __restrict__ mean_out, __half* __restrict__ cur_out,
    float* __restrict__ res, const float* __restrict__ res_init,
    const __half* __restrict__ prev, int n)
{
    __shared__ float sW[15 * C];
    for (int i = threadIdx.x; i < 15 * C; i += 256) sW[i] = wgt[i];
    __syncthreads();
    int gw = (blockIdx.x * 256 + threadIdx.x) >> 5, lane = threadIdx.x & 31;
    if (gw >= n) return;
    int base = off[gw], end = off[gw + 1];
    float4 acc = make_float4(0.f, 0.f, 0.f, 0.f);
    for (int e0 = base; e0 < end; e0 += 32) {
        int cnt = min(32, end - e0);
        int meta = (lane < cnt) ? __ldg(srt + e0 + lane) : 0;
        int j = 0;
        for (; j + 4 <= cnt; j += 4) {
            int m0 = __shfl_sync(0xffffffffu, meta, j + 0);
            int m1 = __shfl_sync(0xffffffffu, meta, j + 1);
            int m2 = __shfl_sync(0xffffffffu, meta, j + 2);
            int m3 = __shfl_sync(0xffffffffu, meta, j + 3);
            float4 v0 = unpack4(__ldg((const uint2*)(src + (size_t)(m0 & 0xFFFF) * C) + lane));
            float4 v1 = unpack4(__ldg((const uint2*)(src + (size_t)(m1 & 0xFFFF) * C) + lane));
            float4 v2 = unpack4(__ldg((const uint2*)(src + (size_t)(m2 & 0xFFFF) * C) + lane));
            float4 v3 = unpack4(__ldg((const uint2*)(src + (size_t)(m3 & 0xFFFF) * C) + lane));
            float4 w0 = *((const float4*)(sW + (((unsigned)m0) >> 16) * C) + lane);
            float4 w1 = *((const float4*)(sW + (((unsigned)m1) >> 16) * C) + lane);
            float4 w2 = *((const float4*)(sW + (((unsigned)m2) >> 16) * C) + lane);
            float4 w3 = *((const float4*)(sW + (((unsigned)m3) >> 16) * C) + lane);
            acc.x += v0.x * w0.x + v1.x * w1.x + v2.x * w2.x + v3.x * w3.x;
            acc.y += v0.y * w0.y + v1.y * w1.y + v2.y * w2.y + v3.y * w3.y;
            acc.z += v0.z * w0.z + v1.z * w1.z + v2.z * w2.z + v3.z * w3.z;
            acc.w += v0.w * w0.w + v1.w * w1.w + v2.w * w2.w + v3.w * w3.w;
        }
        for (; j < cnt; j++) {
            int m0 = __shfl_sync(0xffffffffu, meta, j);
            float4 v0 = unpack4(__ldg((const uint2*)(src + (size_t)(m0 & 0xFFFF) * C) + lane));
            float4 w0 = *((const float4*)(sW + (((unsigned)m0) >> 16) * C) + lane);
            acc.x += v0.x * w0.x; acc.y += v0.y * w0.y;
            acc.z += v0.z * w0.z; acc.w += v0.w * w0.w;
        }
    }
    float inv = 1.0f / fmaxf((float)(end - base), 1.0f);
    float4 m = make_float4(acc.x * inv, acc.y * inv, acc.z * inv, acc.w * inv);
    ((uint2*)(mean_out + (size_t)gw * C))[lane] = pack4(m.x, m.y, m.z, m.w);
    float ss = m.x * m.x + m.y * m.y + m.z * m.z + m.w * m.w;
    ss += __shfl_xor_sync(0xffffffffu, ss, 16);
    ss += __shfl_xor_sync(0xffffffffu, ss, 8);
    ss += __shfl_xor_sync(0xffffffffu, ss, 4);
    ss += __shfl_xor_sync(0xffffffffu, ss, 2);
    ss += __shfl_xor_sync(0xffffffffu, ss, 1);
    float ni = 1.0f / fmaxf(sqrtf(ss), 1e-12f);
    float4 o = make_float4(m.x * ni, m.y * ni, m.z * ni, m.w * ni);
    if (cur_out) ((uint2*)(cur_out + (size_t)gw * C))[lane] = pack4(o.x, o.y, o.z, o.w);
    if (res) {
        float4 pv = unpack4(__ldg((const uint2*)(prev + (size_t)gw * C) + lane));
        float4 r = __ldg((const float4*)(res_init + (size_t)gw * C) + lane);
        r.x += pv.x + o.x; r.y += pv.y + o.y; r.z += pv.z + o.z; r.w += pv.w + o.w;
        ((float4*)(res + (size_t)gw * C))[lane] = r;
    }
}

// ================= preference-graph aggregation (R4 gather; deferred res) ======
__global__ __launch_bounds__(256) void node_agg_csr(
    const int* __restrict__ off, const int* __restrict__ srt,
    const float* __restrict__ aug, const __half* __restrict__ src,
    __half* __restrict__ cur_out, float* __restrict__ res,
    const float* __restrict__ ri0, const float* __restrict__ ri1, int split,
    const __half* __restrict__ prev, int n)
{
    int gw = (blockIdx.x * 256 + threadIdx.x) >> 5, lane = threadIdx.x & 31;
    if (gw >= n) return;
    int base = off[gw], end = off[gw + 1];
    float4 acc = make_float4(0.f, 0.f, 0.f, 0.f);
    for (int e0 = base; e0 < end; e0 += 32) {
        int cnt = min(32, end - e0);
        int meta = 0; float av = 0.f;
        if (lane < cnt) { meta = __ldg(srt + e0 + lane); av = __ldg(aug + e0 + lane); }
        int j = 0;
        for (; j + 4 <= cnt; j += 4) {
            int m0 = __shfl_sync(0xffffffffu, meta, j + 0);
            int m1 = __shfl_sync(0xffffffffu, meta, j + 1);
            int m2 = __shfl_sync(0xffffffffu, meta, j + 2);
            int m3 = __shfl_sync(0xffffffffu, meta, j + 3);
            float a0 = __shfl_sync(0xffffffffu, av, j + 0);
            float a1 = __shfl_sync(0xffffffffu, av, j + 1);
            float a2 = __shfl_sync(0xffffffffu, av, j + 2);
            float a3 = __shfl_sync(0xffffffffu, av, j + 3);
            float4 v0 = unpack4(__ldg((const uint2*)(src + (size_t)m0 * C) + lane));
            float4 v1 = unpack4(__ldg((const uint2*)(src + (size_t)m1 * C) + lane));
            float4 v2 = unpack4(__ldg((const uint2*)(src + (size_t)m2 * C) + lane));
            float4 v3 = unpack4(__ldg((const uint2*)(src + (size_t)m3 * C) + lane));
            acc.x += v0.x * a0 + v1.x * a1 + v2.x * a2 + v3.x * a3;
            acc.y += v0.y * a0 + v1.y * a1 + v2.y * a2 + v3.y * a3;
            acc.z += v0.z * a0 + v1.z * a1 + v2.z * a2 + v3.z * a3;
            acc.w += v0.w * a0 + v1.w * a1 + v2.w * a2 + v3.w * a3;
        }
        for (; j < cnt; j++) {
            int m0 = __shfl_sync(0xffffffffu, meta, j);
            float a0 = __shfl_sync(0xffffffffu, av, j);
            float4 v0 = unpack4(__ldg((const uint2*)(src + (size_t)m0 * C) + lane));
            acc.x += v0.x * a0; acc.y += v0.y * a0;
            acc.z += v0.z * a0; acc.w += v0.w * a0;
        }
    }
    float ss = acc.x * acc.x + acc.y * acc.y + acc.z * acc.z + acc.w * acc.w;
    ss += __shfl_xor_sync(0xffffffffu, ss, 16);
    ss += __shfl_xor_sync(0xffffffffu, ss, 8);
    ss += __shfl_xor_sync(0xffffffffu, ss, 4);
    ss += __shfl_xor_sync(0xffffffffu, ss, 2);
    ss += __shfl_xor_sync(0xffffffffu, ss, 1);
    float ni = 1.0f / fmaxf(sqrtf(ss), 1e-12f);
    float4 o = make_float4(acc.x * ni, acc.y * ni, acc.z * ni, acc.w * ni);
    if (cur_out) ((uint2*)(cur_out + (size_t)gw * C))[lane] = pack4(o.x, o.y, o.z, o.w);
    if (res) {
        const float* rib = (gw < split) ? ri0 + (size_t)gw * C : ri1 + (size_t)(gw - split) * C;
        float4 pv = unpack4(__ldg((const uint2*)(prev + (size_t)gw * C) + lane));
        float4 r = __ldg((const float4*)rib + lane);
        r.x += pv.x + o.x; r.y += pv.y + o.y; r.z += pv.z + o.z; r.w += pv.w + o.w;
        ((float4*)(res + (size_t)gw * C))[lane] = r;
    }
}

// ================= interact-mat aggregation (R4 gather; deferred res) ==========
__global__ __launch_bounds__(256) void user_agg_csr(
    const int* __restrict__ off, const int2* __restrict__ srt,
    const __half* __restrict__ src, __half* __restrict__ cur_out,
    float* __restrict__ res, const float* __restrict__ res_init,
    const __half* __restrict__ prev, int n)
{
    int gw = (blockIdx.x * 256 + threadIdx.x) >> 5, lane = threadIdx.x & 31;
    if (gw >= n) return;
    int base = off[gw], end = off[gw + 1];
    float4 acc = make_float4(0.f, 0.f, 0.f, 0.f);
    for (int e0 = base; e0 < end; e0 += 32) {
        int cnt = min(32, end - e0);
        int mc = 0; float mv = 0.f;
        if (lane < cnt) { int2 p = __ldg(srt + e0 + lane); mc = p.x; mv = __int_as_float(p.y); }
        int j = 0;
        for (; j + 4 <= cnt; j += 4) {
            int c0 = __shfl_sync(0xffffffffu, mc, j + 0);
            int c1 = __shfl_sync(0xffffffffu, mc, j + 1);
            int c2 = __shfl_sync(0xffffffffu, mc, j + 2);
            int c3 = __shfl_sync(0xffffffffu, mc, j + 3);
            float a0 = __shfl_sync(0xffffffffu, mv, j + 0);
            float a1 = __shfl_sync(0xffffffffu, mv, j + 1);
            float a2 = __shfl_sync(0xffffffffu, mv, j + 2);
            float a3 = __shfl_sync(0xffffffffu, mv, j + 3);
            float4 v0 = unpack4(__ldg((const uint2*)(src + (size_t)c0 * C) + lane));
            float4 v1 = unpack4(__ldg((const uint2*)(src + (size_t)c1 * C) + lane));
            float4 v2 = unpack4(__ldg((const uint2*)(src + (size_t)c2 * C) + lane));
            float4 v3 = unpack4(__ldg((const uint2*)(src + (size_t)c3 * C) + lane));
            acc.x += v0.x * a0 + v1.x * a1 + v2.x * a2 + v3.x * a3;
            acc.y += v0.y * a0 + v1.y * a1 + v2.y * a2 + v3.y * a3;
            acc.z += v0.z * a0 + v1.z * a1 + v2.z * a2 + v3.z * a3;
            acc.w += v0.w * a0 + v1.w * a1 + v2.w * a2 + v3.w * a3;
        }
        for (; j < cnt; j++) {
            int c0 = __shfl_sync(0xffffffffu, mc, j);
            float a0 = __shfl_sync(0xffffffffu, mv, j);
            float4 v0 = unpack4(__ldg((const uint2*)(src + (size_t)c0 * C) + lane));
            acc.x += v0.x * a0; acc.y += v0.y * a0;
            acc.z += v0.z * a0; acc.w += v0.w * a0;
        }
    }
    float ss = acc.x * acc.x + acc.y * acc.y + acc.z * acc.z + acc.w * acc.w;
    ss += __shfl_xor_sync(0xffffffffu, ss, 16);
    ss += __shfl_xor_sync(0xffffffffu, ss, 8);
    ss += __shfl_xor_sync(0xffffffffu, ss, 4);
    ss += __shfl_xor_sync(0xffffffffu, ss, 2);
    ss += __shfl_xor_sync(0xffffffffu, ss, 1);
    float ni = 1.0f / fmaxf(sqrtf(ss), 1e-12f);
    float4 o = make_float4(acc.x * ni, acc.y * ni, acc.z * ni, acc.w * ni);
    if (cur_out) ((uint2*)(cur_out + (size_t)gw * C))[lane] = pack4(o.x, o.y, o.z, o.w);
    if (res) {
        float4 pv = unpack4(__ldg((const uint2*)(prev + (size_t)gw * C) + lane));
        float4 r = __ldg((const float4*)(res_init + (size_t)gw * C) + lane);
        r.x += pv.x + o.x; r.y += pv.y + o.y; r.z += pv.z + o.z; r.w += pv.w + o.w;
        ((float4*)(res + (size_t)gw * C))[lane] = r;
    }
}

// ================= host launcher =================
extern "C" void kernel_launch(void* const* d_in, const int* in_sizes, int n_in,
                              void* d_out, int out_size)
{
    const float* user   = (const float*)d_in[0];
    const float* ent    = (const float*)d_in[1];
    const int*   eidx   = (const int*)  d_in[2];
    const int*   etype  = (const int*)  d_in[3];
    const int*   exidx  = (const int*)  d_in[4];
    const int*   irows  = (const int*)  d_in[6];
    const int*   icols  = (const int*)  d_in[7];
    const float* ivals  = (const float*)d_in[8];
    const float* weight = (const float*)d_in[9];
    const float* WQ     = (const float*)d_in[11];
    const float* WK     = (const float*)d_in[12];

    int n_users = in_sizes[0] / C;
    int n_ent   = in_sizes[1] / C;
    int n_nodes = n_users + n_ent;
    int E   = in_sizes[3];
    int EX  = in_sizes[5];
    int NNZ = in_sizes[6];

    size_t UB = (size_t)n_users * C;
    size_t EB = (size_t)n_ent * C;

    float *augp;
    __half *hNodeA, *hNodeB, *hEntB, *hEntM, *hEntM2, *hUserB, *hQ, *hK, *WT;
    float2* exps;
    int *srt_e, *srt_x, *off3, *cur3, *deg3, *part3;
    int2* srt_i;
    cudaGetSymbolAddress((void**)&hNodeA, g_hNodeA);
    cudaGetSymbolAddress((void**)&hNodeB, g_hNodeB);
    cudaGetSymbolAddress((void**)&hEntB,  g_hEntB);
    cudaGetSymbolAddress((void**)&hEntM,  g_hEntM);
    cudaGetSymbolAddress((void**)&hEntM2, g_hEntM2);
    cudaGetSymbolAddress((void**)&hUserB, g_hUserB);
    cudaGetSymbolAddress((void**)&hQ,     g_hQ);
    cudaGetSymbolAddress((void**)&hK,     g_hK);
    cudaGetSymbolAddress((void**)&WT,     g_WT);
    cudaGetSymbolAddress((void**)&augp,   g_aug);
    cudaGetSymbolAddress((void**)&exps,   g_exps);
    cudaGetSymbolAddress((void**)&srt_e,  g_srt_ent);
    cudaGetSymbolAddress((void**)&srt_x,  g_srt_x);
    cudaGetSymbolAddress((void**)&srt_i,  g_srt_i);
    cudaGetSymbolAddress((void**)&off3,   g_off3);
    cudaGetSymbolAddress((void**)&cur3,   g_cur3);
    cudaGetSymbolAddress((void**)&deg3,   g_deg3);
    cudaGetSymbolAddress((void**)&part3,  g_part3);

    int* off_e = off3;
    int* off_n = off3 + OFFS;
    int* off_u = off3 + 2 * OFFS;

    float* out = (float*)d_out;
    float* user_res = out;              // [n_users, C]
    float* ent_res  = out + UB;         // [n_ent, C]
    float* node_res = out + UB + EB;    // [n_nodes, C]

    const int* eh = eidx;          const int* et = eidx + E;
    const int* xh = exidx;         const int* xt = exidx + EX;

    {
        size_t n4 = (size_t)n_nodes * 32;
        conv2<<<(unsigned)((n4 + 255) / 256), 256>>>(user, ent, UB / 4, n4, hNodeA);
    }
    wt_conv<<<(2 * C * C + 255) / 256, 256>>>(WQ, WK, WT);

    // ---- batched CSR build for the 3 graphs ----
    cudaMemsetAsync(deg3, 0, 3 * DEGS * 4);
    {
        int tot = E + EX + NNZ;
        hist3<<<(tot + 255) / 256, 256>>>(eh, E, xh, EX, irows, NNZ, deg3);
    }
    {
        dim3 g((n_nodes + 1023) >> 10, 3);
        scan_block3<<<g, 1024>>>(deg3, off3, part3, n_ent, n_nodes, n_users);
        scan_part3<<<1, 96>>>(part3);
        dim3 g2((n_nodes + 256) / 256 + 1, 3);
        add_offs3<<<g2, 256>>>(off3, part3, n_ent, n_nodes, n_users);
    }
    cudaMemcpyAsync(cur3, off3, 3 * OFFS * 4, cudaMemcpyDeviceToDevice);
    {
        int tot = E + EX + NNZ;
        scat3<<<(tot + 255) / 256, 256>>>(eh, et, etype, E, xh, xt, EX,
                                          irows, icols, ivals, NNZ,
                                          cur3, srt_e, srt_x, srt_i);
    }

    // ---- Q/K projections (main stream) ----
    {
        int smem = (SB_H + SA_H) * 2;
        cudaFuncSetAttribute(qk_mma, cudaFuncAttributeMaxDynamicSharedMemorySize, smem);
        qk_mma<<<(n_nodes + 63) / 64, 256, smem>>>(hNodeA, WT, hQ, hK, n_nodes);
    }

    int gbN = (n_nodes * 32 + 255) / 256;
    int gbE = (n_ent   * 32 + 255) / 256;
    int gbU = (n_users * 32 + 255) / 256;

    // ---- fork: stream A handles attn -> node1 -> node2 ----
    cudaEventRecord(g_hx.evFork, 0);
    cudaStreamWaitEvent(g_hx.sA, g_hx.evFork, 0);
    attn_csr<<<gbN, 256, 0, g_hx.sA>>>(off_n, srt_x, hQ, hK, exps, augp, n_nodes);
    node_agg_csr<<<gbN, 256, 0, g_hx.sA>>>(
        off_n, srt_x, augp, hNodeA, hNodeB, (float*)0,
        user, ent, n_users, (const __half*)0, n_nodes);
    node_agg_csr<<<gbN, 256, 0, g_hx.sA>>>(
        off_n, srt_x, augp, hNodeB, (__half*)0, node_res,
        user, ent, n_users, hNodeB, n_nodes);
    cudaEventRecord(g_hx.evA, g_hx.sA);

    // ---- main: ent1 ----
    ent_agg_csr<<<gbE, 256>>>(
        off_e, srt_e, hNodeA + UB, weight, hEntM, hEntB,
        (float*)0, (const float*)0, (const __half*)0, n_ent);

    // ---- fork: stream B handles user1 (needs entM1 only) ----
    cudaEventRecord(g_hx.evE1, 0);
    cudaStreamWaitEvent(g_hx.sB, g_hx.evE1, 0);
    user_agg_csr<<<gbU, 256, 0, g_hx.sB>>>(
        off_u, srt_i, hEntM, hUserB, (float*)0, (const float*)0,
        (const __half*)0, n_users);
    cudaEventRecord(g_hx.evB, g_hx.sB);

    // ---- main: ent2 (writes ent_res) ----
    ent_agg_csr<<<gbE, 256>>>(
        off_e, srt_e, hEntB, weight, hEntM2, (__half*)0,
        ent_res, ent, hEntB, n_ent);

    // ---- main: user2 (needs entM2 [main-ordered] + userB [evB]) ----
    cudaStreamWaitEvent(0, g_hx.evB, 0);
    user_agg_csr<<<gbU, 256>>>(
        off_u, srt_i, hEntM2, (__half*)0, user_res, user, hUserB, n_users);

    // ---- join stream A ----
    cudaStreamWaitEvent(0, g_hx.evA, 0);
}

// round 9
// speedup vs baseline: 1.1728x; 1.0117x over previous
#include <cuda_runtime.h>
#include <cuda_fp16.h>

#define C 128
#define MAX_USERS   50000
#define MAX_ENT     50000
#define MAX_NODES  100000
#define MAX_E     1000000
#define DEGS 100000          // deg segment stride
#define OFFS 100008          // off/cursor segment stride
#define PS   132             // partials segment stride

// ---------------- scratch (allocation-free: __device__ globals) ----------------
__device__ __half g_hNodeA [(size_t)MAX_NODES * C];
__device__ __half g_hNodeB [(size_t)MAX_NODES * C];
__device__ __half g_hEntB  [(size_t)MAX_ENT   * C];
__device__ __half g_hEntM  [(size_t)MAX_ENT   * C];   // hop-1 entity mean
__device__ __half g_hEntM2 [(size_t)MAX_ENT   * C];   // hop-2 entity mean
__device__ __half g_hUserB [(size_t)MAX_USERS * C];   // hop-1 user norm
__device__ __half g_hQ     [(size_t)MAX_NODES * C];
__device__ __half g_hK     [(size_t)MAX_NODES * C];
__device__ __half g_WT     [2 * C * C];               // [mat][n][k] fp16 (W transposed)
__device__ int    g_srt_ent[MAX_E];
__device__ int    g_srt_x  [MAX_E];
__device__ int2   g_srt_i  [MAX_E];
__device__ float2 g_exps   [MAX_E];
__device__ float  g_aug    [MAX_E];
__device__ int    g_deg3   [3 * DEGS];
__device__ int    g_off3   [3 * OFFS];
__device__ int    g_cur3   [3 * OFFS];
__device__ int    g_part3  [3 * PS];

// ---------------- streams/events (host objects, created once pre-checkpoint) ----
struct HxStreams {
    cudaStream_t sA, sB;
    cudaEvent_t evFork, evConv, evCSR, evE1, evA, evB;
    HxStreams() {
        cudaStreamCreateWithFlags(&sA, cudaStreamNonBlocking);
        cudaStreamCreateWithFlags(&sB, cudaStreamNonBlocking);
        cudaEventCreateWithFlags(&evFork, cudaEventDisableTiming);
        cudaEventCreateWithFlags(&evConv, cudaEventDisableTiming);
        cudaEventCreateWithFlags(&evCSR,  cudaEventDisableTiming);
        cudaEventCreateWithFlags(&evE1,   cudaEventDisableTiming);
        cudaEventCreateWithFlags(&evA,    cudaEventDisableTiming);
        cudaEventCreateWithFlags(&evB,    cudaEventDisableTiming);
    }
};
static HxStreams g_hx;

// ---------------- half pack/unpack ----------------
__device__ __forceinline__ uint2 pack4(float a, float b, float c, float d) {
    __half2 h0 = __floats2half2_rn(a, b);
    __half2 h1 = __floats2half2_rn(c, d);
    uint2 r; r.x = *(unsigned*)&h0; r.y = *(unsigned*)&h1; return r;
}
__device__ __forceinline__ float4 unpack4(uint2 v) {
    __half2 h0 = *(__half2*)&v.x, h1 = *(__half2*)&v.y;
    float2 f0 = __half22float2(h0), f1 = __half22float2(h1);
    return make_float4(f0.x, f0.y, f1.x, f1.y);
}

// ================= fp32 (user|ent) -> fp16 concat =================
__global__ __launch_bounds__(256) void conv2(const float* __restrict__ a,
                                             const float* __restrict__ b,
                                             size_t n4a, size_t n4, __half* __restrict__ dst)
{
    size_t i = (size_t)blockIdx.x * 256 + threadIdx.x;
    if (i >= n4) return;
    float4 v = (i < n4a) ? __ldg((const float4*)a + i) : __ldg((const float4*)b + (i - n4a));
    ((uint2*)dst)[i] = pack4(v.x, v.y, v.z, v.w);
}

// ================= W fp32 [k][n] -> fp16 transposed [mat][n][k] =================
__global__ __launch_bounds__(256) void wt_conv(const float* __restrict__ WQ,
                                               const float* __restrict__ WK,
                                               __half* __restrict__ WT)
{
    int i = blockIdx.x * 256 + threadIdx.x;
    if (i >= 2 * C * C) return;
    int mat = i >> 14, r = i & 16383;
    int k = r >> 7, n = r & 127;
    float v = mat ? __ldg(WK + r) : __ldg(WQ + r);
    WT[mat * C * C + n * C + k] = __float2half_rn(v);
}

// ================= CSR build (batched over the 3 graphs) =================
__global__ __launch_bounds__(256) void zero_deg3(int* __restrict__ deg3)
{
    int i = blockIdx.x * 256 + threadIdx.x;
    if (i < 3 * DEGS) deg3[i] = 0;
}

__global__ __launch_bounds__(256) void hist3(
    const int* __restrict__ h_e, int E1,
    const int* __restrict__ h_x, int E2,
    const int* __restrict__ h_u, int E3, int* __restrict__ deg3)
{
    int i = blockIdx.x * 256 + threadIdx.x;
    if (i < E1) { atomicAdd(deg3 + __ldg(h_e + i), 1); return; }
    i -= E1;
    if (i < E2) { atomicAdd(deg3 + DEGS + __ldg(h_x + i), 1); return; }
    i -= E2;
    if (i < E3) atomicAdd(deg3 + 2 * DEGS + __ldg(h_u + i), 1);
}

__global__ __launch_bounds__(1024) void scan_block3(const int* __restrict__ deg3,
                                                    int* __restrict__ off3, int* __restrict__ part3,
                                                    int n0, int n1, int n2)
{
    __shared__ int ws[32];
    int y = blockIdx.y;
    int n = (y == 0) ? n0 : ((y == 1) ? n1 : n2);
    const int* deg = deg3 + y * DEGS;
    int* off = off3 + y * OFFS;
    int* part = part3 + y * PS;
    int t = threadIdx.x;
    int gid = blockIdx.x * 1024 + t;
    int v = (gid < n) ? deg[gid] : 0;
    int x = v;
#pragma unroll
    for (int d = 1; d < 32; d <<= 1) {
        int yv = __shfl_up_sync(0xffffffffu, x, d);
        if ((t & 31) >= d) x += yv;
    }
    if ((t & 31) == 31) ws[t >> 5] = x;
    __syncthreads();
    if (t < 32) {
        int s = ws[t];
#pragma unroll
        for (int d = 1; d < 32; d <<= 1) {
            int yv = __shfl_up_sync(0xffffffffu, s, d);
            if (t >= d) s += yv;
        }
        ws[t] = s;
    }
    __syncthreads();
    int excl = x - v + ((t >= 32) ? ws[(t >> 5) - 1] : 0);
    if (gid < n) off[gid] = excl;
    if (t == 1023) part[blockIdx.x] = excl + v;
}

__global__ void scan_part3(int* __restrict__ part3)
{
    int t = threadIdx.x;            // 96 threads
    int w = t >> 5, lane = t & 31;
    int* part = part3 + w * PS;
    int v[4];
#pragma unroll
    for (int i = 0; i < 4; i++) v[i] = part[lane * 4 + i];
    int loc = v[0] + v[1] + v[2] + v[3];
    int x = loc;
#pragma unroll
    for (int d = 1; d < 32; d <<= 1) {
        int y = __shfl_up_sync(0xffffffffu, x, d);
        if (lane >= d) x += y;
    }
    int excl = x - loc;
#pragma unroll
    for (int i = 0; i < 4; i++) { part[lane * 4 + i] = excl; excl += v[i]; }
}

__global__ __launch_bounds__(256) void add_offs3(int* __restrict__ off3,
                                                 int* __restrict__ cur3,
                                                 const int* __restrict__ part3,
                                                 int n0, int n1, int n2)
{
    int y = blockIdx.y;
    int n = (y == 0) ? n0 : ((y == 1) ? n1 : n2);
    int* off = off3 + y * OFFS;
    int* cur = cur3 + y * OFFS;
    const int* part = part3 + y * PS;
    int i = blockIdx.x * 256 + threadIdx.x;
    if (i < n) {
        int v = off[i] + part[i >> 10];
        off[i] = v;
        cur[i] = v;
    } else if (i == n) {
        off[i] = part[(n + 1023) >> 10];
    }
}

__global__ __launch_bounds__(256) void scat3(
    const int* __restrict__ eh, const int* __restrict__ et, const int* __restrict__ ety, int E1,
    const int* __restrict__ xh, const int* __restrict__ xt, int E2,
    const int* __restrict__ ir, const int* __restrict__ ic, const float* __restrict__ iv, int E3,
    int* __restrict__ cur3, int* __restrict__ srt_e, int* __restrict__ srt_x, int2* __restrict__ srt_i)
{
    int i = blockIdx.x * 256 + threadIdx.x;
    if (i < E1) {
        int p = atomicAdd(cur3 + __ldg(eh + i), 1);
        srt_e[p] = __ldg(et + i) | ((__ldg(ety + i) - 1) << 16);
        return;
    }
    i -= E1;
    if (i < E2) {
        int p = atomicAdd(cur3 + OFFS + __ldg(xh + i), 1);
        srt_x[p] = __ldg(xt + i);
        return;
    }
    i -= E2;
    if (i < E3) {
        int p = atomicAdd(cur3 + 2 * OFFS + __ldg(ir + i), 1);
        srt_i[p] = make_int2(__ldg(ic + i), __float_as_int(__ldg(iv + i)));
    }
}

// ================= Q/K projection via HMMA =================
#define SB_H (2 * 128 * 136)
#define SA_H (64 * 136)
__global__ __launch_bounds__(256) void qk_mma(
    const __half* __restrict__ node, const __half* __restrict__ WT,
    __half* __restrict__ Q, __half* __restrict__ K, int n)
{
    extern __shared__ __half sh[];
    __half* sB = sh;            // [mat*128 + n][136]
    __half* sA = sh + SB_H;     // [row][136]
    int t = threadIdx.x;
    int row0 = blockIdx.x * 64;

    for (int i = t; i < 4096; i += 256) {
        uint4 v = __ldg((const uint4*)WT + i);
        int nn = i >> 4, k8 = (i & 15) << 3;
        *(uint4*)(sB + nn * 136 + k8) = v;
    }
    for (int i = t; i < 1024; i += 256) {
        int r = i >> 4, k8 = (i & 15) << 3;
        int gr = row0 + r;
        uint4 v = make_uint4(0u, 0u, 0u, 0u);
        if (gr < n) v = __ldg((const uint4*)(node + (size_t)gr * C) + (i & 15));
        *(uint4*)(sA + r * 136 + k8) = v;
    }
    __syncthreads();

    int lane = t & 31, wid = t >> 5;
    int rg = wid & 3, cg = wid >> 2;
    int arow = rg * 16 + (lane >> 2);
    int kq = (lane & 3) * 2;

#pragma unroll
    for (int mat = 0; mat < 2; mat++) {
        float acc[8][4];
#pragma unroll
        for (int nt = 0; nt < 8; nt++)
#pragma unroll
            for (int c = 0; c < 4; c++) acc[nt][c] = 0.f;

#pragma unroll
        for (int kk = 0; kk < 128; kk += 16) {
            unsigned a0 = *(unsigned*)(sA + arow * 136 + kk + kq);
            unsigned a1 = *(unsigned*)(sA + (arow + 8) * 136 + kk + kq);
            unsigned a2 = *(unsigned*)(sA + arow * 136 + kk + kq + 8);
            unsigned a3 = *(unsigned*)(sA + (arow + 8) * 136 + kk + kq + 8);
#pragma unroll
            for (int nt = 0; nt < 8; nt++) {
                int nn = mat * 128 + cg * 64 + nt * 8 + (lane >> 2);
                unsigned b0 = *(unsigned*)(sB + nn * 136 + kk + kq);
                unsigned b1 = *(unsigned*)(sB + nn * 136 + kk + kq + 8);
                asm volatile(
                    "mma.sync.aligned.m16n8k16.row.col.f32.f16.f16.f32 "
                    "{%0,%1,%2,%3}, {%4,%5,%6,%7}, {%8,%9}, {%0,%1,%2,%3};"
                    : "+f"(acc[nt][0]), "+f"(acc[nt][1]), "+f"(acc[nt][2]), "+f"(acc[nt][3])
                    : "r"(a0), "r"(a1), "r"(a2), "r"(a3), "r"(b0), "r"(b1));
            }
        }

        __half* outb = mat ? K : Q;
        int grow = row0 + rg * 16 + (lane >> 2);
#pragma unroll
        for (int nt = 0; nt < 8; nt++) {
            int col = cg * 64 + nt * 8 + (lane & 3) * 2;
            if (grow < n) {
                __half2 h = __floats2half2_rn(acc[nt][0], acc[nt][1]);
                *(__half2*)(outb + (size_t)grow * C + col) = h;
            }
            if (grow + 8 < n) {
                __half2 h = __floats2half2_rn(acc[nt][2], acc[nt][3]);
                *(__half2*)(outb + (size_t)(grow + 8) * C + col) = h;
            }
        }
    }
}

// ================= fused attention (CSR) =================
__global__ __launch_bounds__(256) void attn_csr(
    const int* __restrict__ off, const int* __restrict__ srt,
    const __half* __restrict__ Q, const __half* __restrict__ K,
    float2* __restrict__ exps, float* __restrict__ aug, int n)
{
    int gw = (blockIdx.x * 256 + threadIdx.x) >> 5, lane = threadIdx.x & 31;
    if (gw >= n) return;
    int base = off[gw], end = off[gw + 1];
    if (base == end) return;
    float4 q = unpack4(__ldg((const uint2*)(Q + (size_t)gw * C) + lane));
    float z0 = 0.f, z1 = 0.f;
    for (int e0 = base; e0 < end; e0 += 32) {
        int cnt = min(32, end - e0);
        int meta = (lane < cnt) ? __ldg(srt + e0 + lane) : 0;
        float my0 = 0.f, my1 = 0.f;
        for (int j = 0; j < cnt; j++) {
            int tl = __shfl_sync(0xffffffffu, meta, j);
            float4 k4 = unpack4(__ldg((const uint2*)(K + (size_t)tl * C) + lane));
            float p = q.x * k4.x + q.y * k4.y + q.z * k4.z + q.w * k4.w;
            p += __shfl_xor_sync(0xffffffffu, p, 8);
            p += __shfl_xor_sync(0xffffffffu, p, 4);
            p += __shfl_xor_sync(0xffffffffu, p, 2);
            p += __shfl_xor_sync(0xffffffffu, p, 1);
            float po = __shfl_xor_sync(0xffffffffu, p, 16);
            float s0 = (lane < 16) ? p : po;
            float s1 = (lane < 16) ? po : p;
            float ex0 = __expf(s0 * 0.125f);
            float ex1 = __expf(s1 * 0.125f);
            z0 += ex0; z1 += ex1;
            if (lane == j) { my0 = ex0; my1 = ex1; }
        }
        if (lane < cnt) exps[e0 + lane] = make_float2(my0, my1);
    }
    float iz0 = 0.5f / z0, iz1 = 0.5f / z1;
    for (int e0 = base; e0 < end; e0 += 32) {
        int cnt = min(32, end - e0);
        if (lane < cnt) {
            float2 ex = exps[e0 + lane];
            aug[e0 + lane] = ex.x * iz0 + ex.y * iz1;
        }
    }
}

// ================= entity KG aggregation (MLP=8 gather; fused mean+norm+res) ====
__global__ __launch_bounds__(256) void ent_agg_csr(
    const int* __restrict__ off, const int* __restrict__ srt,
    const __half* __restrict__ src, const float* __restrict__ wgt,
    __half* __restrict__ mean_out, __half* __restrict__ cur_out,
    float* __restrict__ res, const float* __restrict__ res_init,
    const __half* __restrict__ prev, int n)
{
    __shared__ float sW[15 * C];
    for (int i = threadIdx.x; i < 15 * C; i += 256) sW[i] = wgt[i];
    __syncthreads();
    int gw = (blockIdx.x * 256 + threadIdx.x) >> 5, lane = threadIdx.x & 31;
    if (gw >= n) return;
    int base = off[gw], end = off[gw + 1];
    float4 acc = make_float4(0.f, 0.f, 0.f, 0.f);
    for (int e0 = base; e0 < end; e0 += 32) {
        int cnt = min(32, end - e0);
        int meta = (lane < cnt) ? __ldg(srt + e0 + lane) : 0;
        int j = 0;
        for (; j + 8 <= cnt; j += 8) {
            int mm[8]; uint2 u[8];
#pragma unroll
            for (int q = 0; q < 8; q++) {
                mm[q] = __shfl_sync(0xffffffffu, meta, j + q);
                u[q] = __ldg((const uint2*)(src + (size_t)(mm[q] & 0xFFFF) * C) + lane);
            }
#pragma unroll
            for (int q = 0; q < 8; q++) {
                float4 v = unpack4(u[q]);
                float4 w = *((const float4*)(sW + (((unsigned)mm[q]) >> 16) * C) + lane);
                acc.x += v.x * w.x; acc.y += v.y * w.y;
                acc.z += v.z * w.z; acc.w += v.w * w.w;
            }
        }
        for (; j < cnt; j++) {
            int m0 = __shfl_sync(0xffffffffu, meta, j);
            float4 v0 = unpack4(__ldg((const uint2*)(src + (size_t)(m0 & 0xFFFF) * C) + lane));
            float4 w0 = *((const float4*)(sW + (((unsigned)m0) >> 16) * C) + lane);
            acc.x += v0.x * w0.x; acc.y += v0.y * w0.y;
            acc.z += v0.z * w0.z; acc.w += v0.w * w0.w;
        }
    }
    float inv = 1.0f / fmaxf((float)(end - base), 1.0f);
    float4 m = make_float4(acc.x * inv, acc.y * inv, acc.z * inv, acc.w * inv);
    ((uint2*)(mean_out + (size_t)gw * C))[lane] = pack4(m.x, m.y, m.z, m.w);
    float ss = m.x * m.x + m.y * m.y + m.z * m.z + m.w * m.w;
    ss += __shfl_xor_sync(0xffffffffu, ss, 16);
    ss += __shfl_xor_sync(0xffffffffu, ss, 8);
    ss += __shfl_xor_sync(0xffffffffu, ss, 4);
    ss += __shfl_xor_sync(0xffffffffu, ss, 2);
    ss += __shfl_xor_sync(0xffffffffu, ss, 1);
    float ni = 1.0f / fmaxf(sqrtf(ss), 1e-12f);
    float4 o = make_float4(m.x * ni, m.y * ni, m.z * ni, m.w * ni);
    if (cur_out) ((uint2*)(cur_out + (size_t)gw * C))[lane] = pack4(o.x, o.y, o.z, o.w);
    if (res) {
        float4 pv = unpack4(__ldg((const uint2*)(prev + (size_t)gw * C) + lane));
        float4 r = __ldg((const float4*)(res_init + (size_t)gw * C) + lane);
        r.x += pv.x + o.x; r.y += pv.y + o.y; r.z += pv.z + o.z; r.w += pv.w + o.w;
        ((float4*)(res + (size_t)gw * C))[lane] = r;
    }
}

// ================= preference-graph aggregation (MLP=8 gather; deferred res) ======
__global__ __launch_bounds__(256) void node_agg_csr(
    const int* __restrict__ off, const int* __restrict__ srt,
    const float* __restrict__ aug, const __half* __restrict__ src,
    __half* __restrict__ cur_out, float* __restrict__ res,
    const float* __restrict__ ri0, const float* __restrict__ ri1, int split,
    const __half* __restrict__ prev, int n)
{
    int gw = (blockIdx.x * 256 + threadIdx.x) >> 5, lane = threadIdx.x & 31;
    if (gw >= n) return;
    int base = off[gw], end = off[gw + 1];
    float4 acc = make_float4(0.f, 0.f, 0.f, 0.f);
    for (int e0 = base; e0 < end; e0 += 32) {
        int cnt = min(32, end - e0);
        int meta = 0; float av = 0.f;
        if (lane < cnt) { meta = __ldg(srt + e0 + lane); av = __ldg(aug + e0 + lane); }
        int j = 0;
        for (; j + 8 <= cnt; j += 8) {
            float aa[8]; uint2 u[8];
#pragma unroll
            for (int q = 0; q < 8; q++) {
                int m = __shfl_sync(0xffffffffu, meta, j + q);
                aa[q] = __shfl_sync(0xffffffffu, av, j + q);
                u[q] = __ldg((const uint2*)(src + (size_t)m * C) + lane);
            }
#pragma unroll
            for (int q = 0; q < 8; q++) {
                float4 v = unpack4(u[q]);
                acc.x += v.x * aa[q]; acc.y += v.y * aa[q];
                acc.z += v.z * aa[q]; acc.w += v.w * aa[q];
            }
        }
        for (; j < cnt; j++) {
            int m0 = __shfl_sync(0xffffffffu, meta, j);
            float a0 = __shfl_sync(0xffffffffu, av, j);
            float4 v0 = unpack4(__ldg((const uint2*)(src + (size_t)m0 * C) + lane));
            acc.x += v0.x * a0; acc.y += v0.y * a0;
            acc.z += v0.z * a0; acc.w += v0.w * a0;
        }
    }
    float ss = acc.x * acc.x + acc.y * acc.y + acc.z * acc.z + acc.w * acc.w;
    ss += __shfl_xor_sync(0xffffffffu, ss, 16);
    ss += __shfl_xor_sync(0xffffffffu, ss, 8);
    ss += __shfl_xor_sync(0xffffffffu, ss, 4);
    ss += __shfl_xor_sync(0xffffffffu, ss, 2);
    ss += __shfl_xor_sync(0xffffffffu, ss, 1);
    float ni = 1.0f / fmaxf(sqrtf(ss), 1e-12f);
    float4 o = make_float4(acc.x * ni, acc.y * ni, acc.z * ni, acc.w * ni);
    if (cur_out) ((uint2*)(cur_out + (size_t)gw * C))[lane] = pack4(o.x, o.y, o.z, o.w);
    if (res) {
        const float* rib = (gw < split) ? ri0 + (size_t)gw * C : ri1 + (size_t)(gw - split) * C;
        float4 pv = unpack4(__ldg((const uint2*)(prev + (size_t)gw * C) + lane));
        float4 r = __ldg((const float4*)rib + lane);
        r.x += pv.x + o.x; r.y += pv.y + o.y; r.z += pv.z + o.z; r.w += pv.w + o.w;
        ((float4*)(res + (size_t)gw * C))[lane] = r;
    }
}

// ================= interact-mat aggregation (MLP=8 gather; deferred res) ==========
__global__ __launch_bounds__(256) void user_agg_csr(
    const int* __restrict__ off, const int2* __restrict__ srt,
    const __half* __restrict__ src, __half* __restrict__ cur_out,
    float* __restrict__ res, const float* __restrict__ res_init,
    const __half* __restrict__ prev, int n)
{
    int gw = (blockIdx.x * 256 + threadIdx.x) >> 5, lane = threadIdx.x & 31;
    if (gw >= n) return;
    int base = off[gw], end = off[gw + 1];
    float4 acc = make_float4(0.f, 0.f, 0.f, 0.f);
    for (int e0 = base; e0 < end; e0 += 32) {
        int cnt = min(32, end - e0);
        int mc = 0; float mv = 0.f;
        if (lane < cnt) { int2 p = __ldg(srt + e0 + lane); mc = p.x; mv = __int_as_float(p.y); }
        int j = 0;
        for (; j + 8 <= cnt; j += 8) {
            float aa[8]; uint2 u[8];
#pragma unroll
            for (int q = 0; q < 8; q++) {
                int m = __shfl_sync(0xffffffffu, mc, j + q);
                aa[q] = __shfl_sync(0xffffffffu, mv, j + q);
                u[q] = __ldg((const uint2*)(src + (size_t)m * C) + lane);
            }
#pragma unroll
            for (int q = 0; q < 8; q++) {
                float4 v = unpack4(u[q]);
                acc.x += v.x * aa[q]; acc.y += v.y * aa[q];
                acc.z += v.z * aa[q]; acc.w += v.w * aa[q];
            }
        }
        for (; j < cnt; j++) {
            int c0 = __shfl_sync(0xffffffffu, mc, j);
            float a0 = __shfl_sync(0xffffffffu, mv, j);
            float4 v0 = unpack4(__ldg((const uint2*)(src + (size_t)c0 * C) + lane));
            acc.x += v0.x * a0; acc.y += v0.y * a0;
            acc.z += v0.z * a0; acc.w += v0.w * a0;
        }
    }
    float ss = acc.x * acc.x + acc.y * acc.y + acc.z * acc.z + acc.w * acc.w;
    ss += __shfl_xor_sync(0xffffffffu, ss, 16);
    ss += __shfl_xor_sync(0xffffffffu, ss, 8);
    ss += __shfl_xor_sync(0xffffffffu, ss, 4);
    ss += __shfl_xor_sync(0xffffffffu, ss, 2);
    ss += __shfl_xor_sync(0xffffffffu, ss, 1);
    float ni = 1.0f / fmaxf(sqrtf(ss), 1e-12f);
    float4 o = make_float4(acc.x * ni, acc.y * ni, acc.z * ni, acc.w * ni);
    if (cur_out) ((uint2*)(cur_out + (size_t)gw * C))[lane] = pack4(o.x, o.y, o.z, o.w);
    if (res) {
        float4 pv = unpack4(__ldg((const uint2*)(prev + (size_t)gw * C) + lane));
        float4 r = __ldg((const float4*)(res_init + (size_t)gw * C) + lane);
        r.x += pv.x + o.x; r.y += pv.y + o.y; r.z += pv.z + o.z; r.w += pv.w + o.w;
        ((float4*)(res + (size_t)gw * C))[lane] = r;
    }
}

// ================= host launcher =================
extern "C" void kernel_launch(void* const* d_in, const int* in_sizes, int n_in,
                              void* d_out, int out_size)
{
    const float* user   = (const float*)d_in[0];
    const float* ent    = (const float*)d_in[1];
    const int*   eidx   = (const int*)  d_in[2];
    const int*   etype  = (const int*)  d_in[3];
    const int*   exidx  = (const int*)  d_in[4];
    const int*   irows  = (const int*)  d_in[6];
    const int*   icols  = (const int*)  d_in[7];
    const float* ivals  = (const float*)d_in[8];
    const float* weight = (const float*)d_in[9];
    const float* WQ     = (const float*)d_in[11];
    const float* WK     = (const float*)d_in[12];

    int n_users = in_sizes[0] / C;
    int n_ent   = in_sizes[1] / C;
    int n_nodes = n_users + n_ent;
    int E   = in_sizes[3];
    int EX  = in_sizes[5];
    int NNZ = in_sizes[6];

    size_t UB = (size_t)n_users * C;
    size_t EB = (size_t)n_ent * C;

    float *augp;
    __half *hNodeA, *hNodeB, *hEntB, *hEntM, *hEntM2, *hUserB, *hQ, *hK, *WT;
    float2* exps;
    int *srt_e, *srt_x, *off3, *cur3, *deg3, *part3;
    int2* srt_i;
    cudaGetSymbolAddress((void**)&hNodeA, g_hNodeA);
    cudaGetSymbolAddress((void**)&hNodeB, g_hNodeB);
    cudaGetSymbolAddress((void**)&hEntB,  g_hEntB);
    cudaGetSymbolAddress((void**)&hEntM,  g_hEntM);
    cudaGetSymbolAddress((void**)&hEntM2, g_hEntM2);
    cudaGetSymbolAddress((void**)&hUserB, g_hUserB);
    cudaGetSymbolAddress((void**)&hQ,     g_hQ);
    cudaGetSymbolAddress((void**)&hK,     g_hK);
    cudaGetSymbolAddress((void**)&WT,     g_WT);
    cudaGetSymbolAddress((void**)&augp,   g_aug);
    cudaGetSymbolAddress((void**)&exps,   g_exps);
    cudaGetSymbolAddress((void**)&srt_e,  g_srt_ent);
    cudaGetSymbolAddress((void**)&srt_x,  g_srt_x);
    cudaGetSymbolAddress((void**)&srt_i,  g_srt_i);
    cudaGetSymbolAddress((void**)&off3,   g_off3);
    cudaGetSymbolAddress((void**)&cur3,   g_cur3);
    cudaGetSymbolAddress((void**)&deg3,   g_deg3);
    cudaGetSymbolAddress((void**)&part3,  g_part3);

    int* off_e = off3;
    int* off_n = off3 + OFFS;
    int* off_u = off3 + 2 * OFFS;

    float* out = (float*)d_out;
    float* user_res = out;              // [n_users, C]
    float* ent_res  = out + UB;         // [n_ent, C]
    float* node_res = out + UB + EB;    // [n_nodes, C]

    const int* eh = eidx;          const int* et = eidx + E;
    const int* xh = exidx;         const int* xt = exidx + EX;

    // ---- fork from origin stream FIRST (required for graph capture) ----
    cudaEventRecord(g_hx.evFork, 0);
    cudaStreamWaitEvent(g_hx.sA, g_hx.evFork, 0);
    cudaStreamWaitEvent(g_hx.sB, g_hx.evFork, 0);

    // ---- stream B: full CSR build (depends only on edge lists) ----
    zero_deg3<<<(3 * DEGS + 255) / 256, 256, 0, g_hx.sB>>>(deg3);
    {
        int tot = E + EX + NNZ;
        hist3<<<(tot + 255) / 256, 256, 0, g_hx.sB>>>(eh, E, xh, EX, irows, NNZ, deg3);
    }
    {
        dim3 g((n_nodes + 1023) >> 10, 3);
        scan_block3<<<g, 1024, 0, g_hx.sB>>>(deg3, off3, part3, n_ent, n_nodes, n_users);
        scan_part3<<<1, 96, 0, g_hx.sB>>>(part3);
        dim3 g2((n_nodes + 256) / 256 + 1, 3);
        add_offs3<<<g2, 256, 0, g_hx.sB>>>(off3, cur3, part3, n_ent, n_nodes, n_users);
    }
    {
        int tot = E + EX + NNZ;
        scat3<<<(tot + 255) / 256, 256, 0, g_hx.sB>>>(eh, et, etype, E, xh, xt, EX,
                                                      irows, icols, ivals, NNZ,
                                                      cur3, srt_e, srt_x, srt_i);
    }
    cudaEventRecord(g_hx.evCSR, g_hx.sB);

    // ---- main: fp16 concat of node embeddings ----
    {
        size_t n4 = (size_t)n_nodes * 32;
        conv2<<<(unsigned)((n4 + 255) / 256), 256>>>(user, ent, UB / 4, n4, hNodeA);
    }
    cudaEventRecord(g_hx.evConv, 0);

    // ---- stream A: wt_conv -> qk_mma -> attn -> node1 -> node2 ----
    wt_conv<<<(2 * C * C + 255) / 256, 256, 0, g_hx.sA>>>(WQ, WK, WT);
    cudaStreamWaitEvent(g_hx.sA, g_hx.evConv, 0);
    {
        int smem = (SB_H + SA_H) * 2;
        cudaFuncSetAttribute(qk_mma, cudaFuncAttributeMaxDynamicSharedMemorySize, smem);
        qk_mma<<<(n_nodes + 63) / 64, 256, smem, g_hx.sA>>>(hNodeA, WT, hQ, hK, n_nodes);
    }
    cudaStreamWaitEvent(g_hx.sA, g_hx.evCSR, 0);

    int gbN = (n_nodes * 32 + 255) / 256;
    int gbE = (n_ent   * 32 + 255) / 256;
    int gbU = (n_users * 32 + 255) / 256;

    attn_csr<<<gbN, 256, 0, g_hx.sA>>>(off_n, srt_x, hQ, hK, exps, augp, n_nodes);
    node_agg_csr<<<gbN, 256, 0, g_hx.sA>>>(
        off_n, srt_x, augp, hNodeA, hNodeB, (float*)0,
        user, ent, n_users, (const __half*)0, n_nodes);
    node_agg_csr<<<gbN, 256, 0, g_hx.sA>>>(
        off_n, srt_x, augp, hNodeB, (__half*)0, node_res,
        user, ent, n_users, hNodeB, n_nodes);
    cudaEventRecord(g_hx.evA, g_hx.sA);

    // ---- main: ent1 (needs conv2 [main order] + CSR) ----
    cudaStreamWaitEvent(0, g_hx.evCSR, 0);
    ent_agg_csr<<<gbE, 256>>>(
        off_e, srt_e, hNodeA + UB, weight, hEntM, hEntB,
        (float*)0, (const float*)0, (const __half*)0, n_ent);
    cudaEventRecord(g_hx.evE1, 0);

    // ---- stream B: user1 (needs entM1) ----
    cudaStreamWaitEvent(g_hx.sB, g_hx.evE1, 0);
    user_agg_csr<<<gbU, 256, 0, g_hx.sB>>>(
        off_u, srt_i, hEntM, hUserB, (float*)0, (const float*)0,
        (const __half*)0, n_users);
    cudaEventRecord(g_hx.evB, g_hx.sB);

    // ---- main: ent2 (writes ent_res) ----
    ent_agg_csr<<<gbE, 256>>>(
        off_e, srt_e, hEntB, weight, hEntM2, (__half*)0,
        ent_res, ent, hEntB, n_ent);

    // ---- main: user2 (needs entM2 [main-ordered] + userB [evB]) ----
    cudaStreamWaitEvent(0, g_hx.evB, 0);
    user_agg_csr<<<gbU, 256>>>(
        off_u, srt_i, hEntM2, (__half*)0, user_res, user, hUserB, n_users);

    // ---- join stream A ----
    cudaStreamWaitEvent(0, g_hx.evA, 0);
}

// round 10
// speedup vs baseline: 1.1963x; 1.0200x over previous
#include <cuda_runtime.h>
#include <cuda_fp16.h>

#define C 128
#define MAX_USERS   50000
#define MAX_ENT     50000
#define MAX_NODES  100000
#define MAX_E     1000000
#define DEGS 100000          // deg segment stride
#define OFFS 100008          // off/cursor segment stride
#define PS   132             // partials segment stride

// ---------------- scratch (allocation-free: __device__ globals) ----------------
__device__ __half g_hNodeA [(size_t)MAX_NODES * C];
__device__ __half g_hNodeB [(size_t)MAX_NODES * C];
__device__ __half g_hEntB  [(size_t)MAX_ENT   * C];
__device__ __half g_hEntM  [(size_t)MAX_ENT   * C];   // hop-1 entity mean
__device__ __half g_hEntM2 [(size_t)MAX_ENT   * C];   // hop-2 entity mean
__device__ __half g_hUserB [(size_t)MAX_USERS * C];   // hop-1 user norm
__device__ __half g_hQ     [(size_t)MAX_NODES * C];
__device__ __half g_hK     [(size_t)MAX_NODES * C];
__device__ __half g_WT     [2 * C * C];               // [mat][n][k] fp16 (W transposed)
__device__ int    g_srt_ent[MAX_E];
__device__ int    g_srt_x  [MAX_E];
__device__ int2   g_srt_i  [MAX_E];
__device__ float2 g_exps   [MAX_E];
__device__ float  g_aug    [MAX_E];
__device__ int    g_deg3   [3 * DEGS];
__device__ int    g_off3   [3 * OFFS];
__device__ int    g_cur3   [3 * OFFS];
__device__ int    g_part3  [3 * PS];

// ---------------- streams/events (host objects, created once pre-checkpoint) ----
struct HxStreams {
    cudaStream_t sA, sB;
    cudaEvent_t evFork, evConv, evCSR, evE1, evA, evB;
    HxStreams() {
        cudaStreamCreateWithFlags(&sA, cudaStreamNonBlocking);
        cudaStreamCreateWithFlags(&sB, cudaStreamNonBlocking);
        cudaEventCreateWithFlags(&evFork, cudaEventDisableTiming);
        cudaEventCreateWithFlags(&evConv, cudaEventDisableTiming);
        cudaEventCreateWithFlags(&evCSR,  cudaEventDisableTiming);
        cudaEventCreateWithFlags(&evE1,   cudaEventDisableTiming);
        cudaEventCreateWithFlags(&evA,    cudaEventDisableTiming);
        cudaEventCreateWithFlags(&evB,    cudaEventDisableTiming);
    }
};
static HxStreams g_hx;

// ---------------- half pack/unpack ----------------
__device__ __forceinline__ uint2 pack4(float a, float b, float c, float d) {
    __half2 h0 = __floats2half2_rn(a, b);
    __half2 h1 = __floats2half2_rn(c, d);
    uint2 r; r.x = *(unsigned*)&h0; r.y = *(unsigned*)&h1; return r;
}
__device__ __forceinline__ float4 unpack4(uint2 v) {
    __half2 h0 = *(__half2*)&v.x, h1 = *(__half2*)&v.y;
    float2 f0 = __half22float2(h0), f1 = __half22float2(h1);
    return make_float4(f0.x, f0.y, f1.x, f1.y);
}

// ================= fp32 (user|ent) -> fp16 concat =================
__global__ __launch_bounds__(256) void conv2(const float* __restrict__ a,
                                             const float* __restrict__ b,
                                             size_t n4a, size_t n4, __half* __restrict__ dst)
{
    size_t i = (size_t)blockIdx.x * 256 + threadIdx.x;
    if (i >= n4) return;
    float4 v = (i < n4a) ? __ldg((const float4*)a + i) : __ldg((const float4*)b + (i - n4a));
    ((uint2*)dst)[i] = pack4(v.x, v.y, v.z, v.w);
}

// ================= W fp32 [k][n] -> fp16 transposed [mat][n][k] =================
__global__ __launch_bounds__(256) void wt_conv(const float* __restrict__ WQ,
                                               const float* __restrict__ WK,
                                               __half* __restrict__ WT)
{
    int i = blockIdx.x * 256 + threadIdx.x;
    if (i >= 2 * C * C) return;
    int mat = i >> 14, r = i & 16383;
    int k = r >> 7, n = r & 127;
    float v = mat ? __ldg(WK + r) : __ldg(WQ + r);
    WT[mat * C * C + n * C + k] = __float2half_rn(v);
}

// ================= CSR build (batched over the 3 graphs) =================
__global__ __launch_bounds__(256) void zero_deg3(int* __restrict__ deg3)
{
    int i = blockIdx.x * 256 + threadIdx.x;
    if (i < 3 * DEGS) deg3[i] = 0;
}

__global__ __launch_bounds__(256) void hist3(
    const int* __restrict__ h_e, int E1,
    const int* __restrict__ h_x, int E2,
    const int* __restrict__ h_u, int E3, int* __restrict__ deg3)
{
    int i = blockIdx.x * 256 + threadIdx.x;
    if (i < E1) { atomicAdd(deg3 + __ldg(h_e + i), 1); return; }
    i -= E1;
    if (i < E2) { atomicAdd(deg3 + DEGS + __ldg(h_x + i), 1); return; }
    i -= E2;
    if (i < E3) atomicAdd(deg3 + 2 * DEGS + __ldg(h_u + i), 1);
}

__global__ __launch_bounds__(1024) void scan_block3(const int* __restrict__ deg3,
                                                    int* __restrict__ off3, int* __restrict__ part3,
                                                    int n0, int n1, int n2)
{
    __shared__ int ws[32];
    int y = blockIdx.y;
    int n = (y == 0) ? n0 : ((y == 1) ? n1 : n2);
    const int* deg = deg3 + y * DEGS;
    int* off = off3 + y * OFFS;
    int* part = part3 + y * PS;
    int t = threadIdx.x;
    int gid = blockIdx.x * 1024 + t;
    int v = (gid < n) ? deg[gid] : 0;
    int x = v;
#pragma unroll
    for (int d = 1; d < 32; d <<= 1) {
        int yv = __shfl_up_sync(0xffffffffu, x, d);
        if ((t & 31) >= d) x += yv;
    }
    if ((t & 31) == 31) ws[t >> 5] = x;
    __syncthreads();
    if (t < 32) {
        int s = ws[t];
#pragma unroll
        for (int d = 1; d < 32; d <<= 1) {
            int yv = __shfl_up_sync(0xffffffffu, s, d);
            if (t >= d) s += yv;
        }
        ws[t] = s;
    }
    __syncthreads();
    int excl = x - v + ((t >= 32) ? ws[(t >> 5) - 1] : 0);
    if (gid < n) off[gid] = excl;
    if (t == 1023) part[blockIdx.x] = excl + v;
}

__global__ void scan_part3(int* __restrict__ part3)
{
    int t = threadIdx.x;            // 96 threads
    int w = t >> 5, lane = t & 31;
    int* part = part3 + w * PS;
    int v[4];
#pragma unroll
    for (int i = 0; i < 4; i++) v[i] = part[lane * 4 + i];
    int loc = v[0] + v[1] + v[2] + v[3];
    int x = loc;
#pragma unroll
    for (int d = 1; d < 32; d <<= 1) {
        int y = __shfl_up_sync(0xffffffffu, x, d);
        if (lane >= d) x += y;
    }
    int excl = x - loc;
#pragma unroll
    for (int i = 0; i < 4; i++) { part[lane * 4 + i] = excl; excl += v[i]; }
}

__global__ __launch_bounds__(256) void add_offs3(int* __restrict__ off3,
                                                 int* __restrict__ cur3,
                                                 const int* __restrict__ part3,
                                                 int n0, int n1, int n2)
{
    int y = blockIdx.y;
    int n = (y == 0) ? n0 : ((y == 1) ? n1 : n2);
    int* off = off3 + y * OFFS;
    int* cur = cur3 + y * OFFS;
    const int* part = part3 + y * PS;
    int i = blockIdx.x * 256 + threadIdx.x;
    if (i < n) {
        int v = off[i] + part[i >> 10];
        off[i] = v;
        cur[i] = v;
    } else if (i == n) {
        off[i] = part[(n + 1023) >> 10];
    }
}

__global__ __launch_bounds__(256) void scat3(
    const int* __restrict__ eh, const int* __restrict__ et, const int* __restrict__ ety, int E1,
    const int* __restrict__ xh, const int* __restrict__ xt, int E2,
    const int* __restrict__ ir, const int* __restrict__ ic, const float* __restrict__ iv, int E3,
    int* __restrict__ cur3, int* __restrict__ srt_e, int* __restrict__ srt_x, int2* __restrict__ srt_i)
{
    int i = blockIdx.x * 256 + threadIdx.x;
    if (i < E1) {
        int p = atomicAdd(cur3 + __ldg(eh + i), 1);
        srt_e[p] = __ldg(et + i) | ((__ldg(ety + i) - 1) << 16);
        return;
    }
    i -= E1;
    if (i < E2) {
        int p = atomicAdd(cur3 + OFFS + __ldg(xh + i), 1);
        srt_x[p] = __ldg(xt + i);
        return;
    }
    i -= E2;
    if (i < E3) {
        int p = atomicAdd(cur3 + 2 * OFFS + __ldg(ir + i), 1);
        srt_i[p] = make_int2(__ldg(ic + i), __float_as_int(__ldg(iv + i)));
    }
}

// ================= Q/K projection via HMMA =================
#define SB_H (2 * 128 * 136)
#define SA_H (64 * 136)
__global__ __launch_bounds__(256) void qk_mma(
    const __half* __restrict__ node, const __half* __restrict__ WT,
    __half* __restrict__ Q, __half* __restrict__ K, int n)
{
    extern __shared__ __half sh[];
    __half* sB = sh;            // [mat*128 + n][136]
    __half* sA = sh + SB_H;     // [row][136]
    int t = threadIdx.x;
    int row0 = blockIdx.x * 64;

    for (int i = t; i < 4096; i += 256) {
        uint4 v = __ldg((const uint4*)WT + i);
        int nn = i >> 4, k8 = (i & 15) << 3;
        *(uint4*)(sB + nn * 136 + k8) = v;
    }
    for (int i = t; i < 1024; i += 256) {
        int r = i >> 4, k8 = (i & 15) << 3;
        int gr = row0 + r;
        uint4 v = make_uint4(0u, 0u, 0u, 0u);
        if (gr < n) v = __ldg((const uint4*)(node + (size_t)gr * C) + (i & 15));
        *(uint4*)(sA + r * 136 + k8) = v;
    }
    __syncthreads();

    int lane = t & 31, wid = t >> 5;
    int rg = wid & 3, cg = wid >> 2;
    int arow = rg * 16 + (lane >> 2);
    int kq = (lane & 3) * 2;

#pragma unroll
    for (int mat = 0; mat < 2; mat++) {
        float acc[8][4];
#pragma unroll
        for (int nt = 0; nt < 8; nt++)
#pragma unroll
            for (int c = 0; c < 4; c++) acc[nt][c] = 0.f;

#pragma unroll
        for (int kk = 0; kk < 128; kk += 16) {
            unsigned a0 = *(unsigned*)(sA + arow * 136 + kk + kq);
            unsigned a1 = *(unsigned*)(sA + (arow + 8) * 136 + kk + kq);
            unsigned a2 = *(unsigned*)(sA + arow * 136 + kk + kq + 8);
            unsigned a3 = *(unsigned*)(sA + (arow + 8) * 136 + kk + kq + 8);
#pragma unroll
            for (int nt = 0; nt < 8; nt++) {
                int nn = mat * 128 + cg * 64 + nt * 8 + (lane >> 2);
                unsigned b0 = *(unsigned*)(sB + nn * 136 + kk + kq);
                unsigned b1 = *(unsigned*)(sB + nn * 136 + kk + kq + 8);
                asm volatile(
                    "mma.sync.aligned.m16n8k16.row.col.f32.f16.f16.f32 "
                    "{%0,%1,%2,%3}, {%4,%5,%6,%7}, {%8,%9}, {%0,%1,%2,%3};"
                    : "+f"(acc[nt][0]), "+f"(acc[nt][1]), "+f"(acc[nt][2]), "+f"(acc[nt][3])
                    : "r"(a0), "r"(a1), "r"(a2), "r"(a3), "r"(b0), "r"(b1));
            }
        }

        __half* outb = mat ? K : Q;
        int grow = row0 + rg * 16 + (lane >> 2);
#pragma unroll
        for (int nt = 0; nt < 8; nt++) {
            int col = cg * 64 + nt * 8 + (lane & 3) * 2;
            if (grow < n) {
                __half2 h = __floats2half2_rn(acc[nt][0], acc[nt][1]);
                *(__half2*)(outb + (size_t)grow * C + col) = h;
            }
            if (grow + 8 < n) {
                __half2 h = __floats2half2_rn(acc[nt][2], acc[nt][3]);
                *(__half2*)(outb + (size_t)(grow + 8) * C + col) = h;
            }
        }
    }
}

// ====== FUSED attention + hop-1 node aggregation ======
// Σ_e aug_e·v_e = iz0·Σ ex0_e·v_e + iz1·Σ ex1_e·v_e  (linearity of softmax agg)
__global__ __launch_bounds__(256) void attn_node1_csr(
    const int* __restrict__ off, const int* __restrict__ srt,
    const __half* __restrict__ Q, const __half* __restrict__ K,
    const __half* __restrict__ nodeA,
    float2* __restrict__ exps, float* __restrict__ aug,
    __half* __restrict__ nodeB, int n)
{
    int gw = (blockIdx.x * 256 + threadIdx.x) >> 5, lane = threadIdx.x & 31;
    if (gw >= n) return;
    int base = off[gw], end = off[gw + 1];
    if (base == end) {
        ((uint2*)(nodeB + (size_t)gw * C))[lane] = pack4(0.f, 0.f, 0.f, 0.f);
        return;
    }
    float4 q = unpack4(__ldg((const uint2*)(Q + (size_t)gw * C) + lane));
    float4 S0 = make_float4(0.f, 0.f, 0.f, 0.f);
    float4 S1 = make_float4(0.f, 0.f, 0.f, 0.f);
    float z0 = 0.f, z1 = 0.f;
    for (int e0 = base; e0 < end; e0 += 32) {
        int cnt = min(32, end - e0);
        int meta = (lane < cnt) ? __ldg(srt + e0 + lane) : 0;
        float my0 = 0.f, my1 = 0.f;
        for (int j = 0; j < cnt; j++) {
            int tl = __shfl_sync(0xffffffffu, meta, j);
            uint2 ku = __ldg((const uint2*)(K + (size_t)tl * C) + lane);
            uint2 vu = __ldg((const uint2*)(nodeA + (size_t)tl * C) + lane);
            float4 k4 = unpack4(ku);
            float p = q.x * k4.x + q.y * k4.y + q.z * k4.z + q.w * k4.w;
            p += __shfl_xor_sync(0xffffffffu, p, 8);
            p += __shfl_xor_sync(0xffffffffu, p, 4);
            p += __shfl_xor_sync(0xffffffffu, p, 2);
            p += __shfl_xor_sync(0xffffffffu, p, 1);
            float po = __shfl_xor_sync(0xffffffffu, p, 16);
            float s0 = (lane < 16) ? p : po;
            float s1 = (lane < 16) ? po : p;
            float ex0 = __expf(s0 * 0.125f);   // warp-uniform (head 0)
            float ex1 = __expf(s1 * 0.125f);   // warp-uniform (head 1)
            z0 += ex0; z1 += ex1;
            float4 v = unpack4(vu);
            S0.x += ex0 * v.x; S0.y += ex0 * v.y; S0.z += ex0 * v.z; S0.w += ex0 * v.w;
            S1.x += ex1 * v.x; S1.y += ex1 * v.y; S1.z += ex1 * v.z; S1.w += ex1 * v.w;
            if (lane == j) { my0 = ex0; my1 = ex1; }
        }
        if (lane < cnt) exps[e0 + lane] = make_float2(my0, my1);
    }
    float iz0 = 0.5f / z0, iz1 = 0.5f / z1;
    // hop-1 node row: l2norm(iz0*S0 + iz1*S1)
    float4 o = make_float4(S0.x * iz0 + S1.x * iz1, S0.y * iz0 + S1.y * iz1,
                           S0.z * iz0 + S1.z * iz1, S0.w * iz0 + S1.w * iz1);
    float ss = o.x * o.x + o.y * o.y + o.z * o.z + o.w * o.w;
    ss += __shfl_xor_sync(0xffffffffu, ss, 16);
    ss += __shfl_xor_sync(0xffffffffu, ss, 8);
    ss += __shfl_xor_sync(0xffffffffu, ss, 4);
    ss += __shfl_xor_sync(0xffffffffu, ss, 2);
    ss += __shfl_xor_sync(0xffffffffu, ss, 1);
    float ni = 1.0f / fmaxf(sqrtf(ss), 1e-12f);
    ((uint2*)(nodeB + (size_t)gw * C))[lane] =
        pack4(o.x * ni, o.y * ni, o.z * ni, o.w * ni);
    // aug for hop-2
    for (int e0 = base; e0 < end; e0 += 32) {
        int cnt = min(32, end - e0);
        if (lane < cnt) {
            float2 ex = exps[e0 + lane];
            aug[e0 + lane] = ex.x * iz0 + ex.y * iz1;
        }
    }
}

// ================= entity KG aggregation (MLP=8 gather; fused mean+norm+res) ====
__global__ __launch_bounds__(256) void ent_agg_csr(
    const int* __restrict__ off, const int* __restrict__ srt,
    const __half* __restrict__ src, const float* __restrict__ wgt,
    __half* __restrict__ mean_out, __half* __restrict__ cur_out,
    float* __restrict__ res, const float* __restrict__ res_init,
    const __half* __restrict__ prev, int n)
{
    __shared__ float sW[15 * C];
    for (int i = threadIdx.x; i < 15 * C; i += 256) sW[i] = wgt[i];
    __syncthreads();
    int gw = (blockIdx.x * 256 + threadIdx.x) >> 5, lane = threadIdx.x & 31;
    if (gw >= n) return;
    int base = off[gw], end = off[gw + 1];
    float4 acc = make_float4(0.f, 0.f, 0.f, 0.f);
    for (int e0 = base; e0 < end; e0 += 32) {
        int cnt = min(32, end - e0);
        int meta = (lane < cnt) ? __ldg(srt + e0 + lane) : 0;
        int j = 0;
        for (; j + 8 <= cnt; j += 8) {
            int mm[8]; uint2 u[8];
#pragma unroll
            for (int q = 0; q < 8; q++) {
                mm[q] = __shfl_sync(0xffffffffu, meta, j + q);
                u[q] = __ldg((const uint2*)(src + (size_t)(mm[q] & 0xFFFF) * C) + lane);
            }
#pragma unroll
            for (int q = 0; q < 8; q++) {
                float4 v = unpack4(u[q]);
                float4 w = *((const float4*)(sW + (((unsigned)mm[q]) >> 16) * C) + lane);
                acc.x += v.x * w.x; acc.y += v.y * w.y;
                acc.z += v.z * w.z; acc.w += v.w * w.w;
            }
        }
        for (; j < cnt; j++) {
            int m0 = __shfl_sync(0xffffffffu, meta, j);
            float4 v0 = unpack4(__ldg((const uint2*)(src + (size_t)(m0 & 0xFFFF) * C) + lane));
            float4 w0 = *((const float4*)(sW + (((unsigned)m0) >> 16) * C) + lane);
            acc.x += v0.x * w0.x; acc.y += v0.y * w0.y;
            acc.z += v0.z * w0.z; acc.w += v0.w * w0.w;
        }
    }
    float inv = 1.0f / fmaxf((float)(end - base), 1.0f);
    float4 m = make_float4(acc.x * inv, acc.y * inv, acc.z * inv, acc.w * inv);
    ((uint2*)(mean_out + (size_t)gw * C))[lane] = pack4(m.x, m.y, m.z, m.w);
    float ss = m.x * m.x + m.y * m.y + m.z * m.z + m.w * m.w;
    ss += __shfl_xor_sync(0xffffffffu, ss, 16);
    ss += __shfl_xor_sync(0xffffffffu, ss, 8);
    ss += __shfl_xor_sync(0xffffffffu, ss, 4);
    ss += __shfl_xor_sync(0xffffffffu, ss, 2);
    ss += __shfl_xor_sync(0xffffffffu, ss, 1);
    float ni = 1.0f / fmaxf(sqrtf(ss), 1e-12f);
    float4 o = make_float4(m.x * ni, m.y * ni, m.z * ni, m.w * ni);
    if (cur_out) ((uint2*)(cur_out + (size_t)gw * C))[lane] = pack4(o.x, o.y, o.z, o.w);
    if (res) {
        float4 pv = unpack4(__ldg((const uint2*)(prev + (size_t)gw * C) + lane));
        float4 r = __ldg((const float4*)(res_init + (size_t)gw * C) + lane);
        r.x += pv.x + o.x; r.y += pv.y + o.y; r.z += pv.z + o.z; r.w += pv.w + o.w;
        ((float4*)(res + (size_t)gw * C))[lane] = r;
    }
}

// ================= preference-graph aggregation hop-2 (MLP=8; writes node_res) ======
__global__ __launch_bounds__(256) void node_agg_csr(
    const int* __restrict__ off, const int* __restrict__ srt,
    const float* __restrict__ aug, const __half* __restrict__ src,
    float* __restrict__ res,
    const float* __restrict__ ri0, const float* __restrict__ ri1, int split,
    const __half* __restrict__ prev, int n)
{
    int gw = (blockIdx.x * 256 + threadIdx.x) >> 5, lane = threadIdx.x & 31;
    if (gw >= n) return;
    int base = off[gw], end = off[gw + 1];
    float4 acc = make_float4(0.f, 0.f, 0.f, 0.f);
    for (int e0 = base; e0 < end; e0 += 32) {
        int cnt = min(32, end - e0);
        int meta = 0; float av = 0.f;
        if (lane < cnt) { meta = __ldg(srt + e0 + lane); av = __ldg(aug + e0 + lane); }
        int j = 0;
        for (; j + 8 <= cnt; j += 8) {
            float aa[8]; uint2 u[8];
#pragma unroll
            for (int q = 0; q < 8; q++) {
                int m = __shfl_sync(0xffffffffu, meta, j + q);
                aa[q] = __shfl_sync(0xffffffffu, av, j + q);
                u[q] = __ldg((const uint2*)(src + (size_t)m * C) + lane);
            }
#pragma unroll
            for (int q = 0; q < 8; q++) {
                float4 v = unpack4(u[q]);
                acc.x += v.x * aa[q]; acc.y += v.y * aa[q];
                acc.z += v.z * aa[q]; acc.w += v.w * aa[q];
            }
        }
        for (; j < cnt; j++) {
            int m0 = __shfl_sync(0xffffffffu, meta, j);
            float a0 = __shfl_sync(0xffffffffu, av, j);
            float4 v0 = unpack4(__ldg((const uint2*)(src + (size_t)m0 * C) + lane));
            acc.x += v0.x * a0; acc.y += v0.y * a0;
            acc.z += v0.z * a0; acc.w += v0.w * a0;
        }
    }
    float ss = acc.x * acc.x + acc.y * acc.y + acc.z * acc.z + acc.w * acc.w;
    ss += __shfl_xor_sync(0xffffffffu, ss, 16);
    ss += __shfl_xor_sync(0xffffffffu, ss, 8);
    ss += __shfl_xor_sync(0xffffffffu, ss, 4);
    ss += __shfl_xor_sync(0xffffffffu, ss, 2);
    ss += __shfl_xor_sync(0xffffffffu, ss, 1);
    float ni = 1.0f / fmaxf(sqrtf(ss), 1e-12f);
    float4 o = make_float4(acc.x * ni, acc.y * ni, acc.z * ni, acc.w * ni);
    const float* rib = (gw < split) ? ri0 + (size_t)gw * C : ri1 + (size_t)(gw - split) * C;
    float4 pv = unpack4(__ldg((const uint2*)(prev + (size_t)gw * C) + lane));
    float4 r = __ldg((const float4*)rib + lane);
    r.x += pv.x + o.x; r.y += pv.y + o.y; r.z += pv.z + o.z; r.w += pv.w + o.w;
    ((float4*)(res + (size_t)gw * C))[lane] = r;
}

// ================= interact-mat aggregation (MLP=8 gather; deferred res) ==========
__global__ __launch_bounds__(256) void user_agg_csr(
    const int* __restrict__ off, const int2* __restrict__ srt,
    const __half* __restrict__ src, __half* __restrict__ cur_out,
    float* __restrict__ res, const float* __restrict__ res_init,
    const __half* __restrict__ prev, int n)
{
    int gw = (blockIdx.x * 256 + threadIdx.x) >> 5, lane = threadIdx.x & 31;
    if (gw >= n) return;
    int base = off[gw], end = off[gw + 1];
    float4 acc = make_float4(0.f, 0.f, 0.f, 0.f);
    for (int e0 = base; e0 < end; e0 += 32) {
        int cnt = min(32, end - e0);
        int mc = 0; float mv = 0.f;
        if (lane < cnt) { int2 p = __ldg(srt + e0 + lane); mc = p.x; mv = __int_as_float(p.y); }
        int j = 0;
        for (; j + 8 <= cnt; j += 8) {
            float aa[8]; uint2 u[8];
#pragma unroll
            for (int q = 0; q < 8; q++) {
                int m = __shfl_sync(0xffffffffu, mc, j + q);
                aa[q] = __shfl_sync(0xffffffffu, mv, j + q);
                u[q] = __ldg((const uint2*)(src + (size_t)m * C) + lane);
            }
#pragma unroll
            for (int q = 0; q < 8; q++) {
                float4 v = unpack4(u[q]);
                acc.x += v.x * aa[q]; acc.y += v.y * aa[q];
                acc.z += v.z * aa[q]; acc.w += v.w * aa[q];
            }
        }
        for (; j < cnt; j++) {
            int c0 = __shfl_sync(0xffffffffu, mc, j);
            float a0 = __shfl_sync(0xffffffffu, mv, j);
            float4 v0 = unpack4(__ldg((const uint2*)(src + (size_t)c0 * C) + lane));
            acc.x += v0.x * a0; acc.y += v0.y * a0;
            acc.z += v0.z * a0; acc.w += v0.w * a0;
        }
    }
    float ss = acc.x * acc.x + acc.y * acc.y + acc.z * acc.z + acc.w * acc.w;
    ss += __shfl_xor_sync(0xffffffffu, ss, 16);
    ss += __shfl_xor_sync(0xffffffffu, ss, 8);
    ss += __shfl_xor_sync(0xffffffffu, ss, 4);
    ss += __shfl_xor_sync(0xffffffffu, ss, 2);
    ss += __shfl_xor_sync(0xffffffffu, ss, 1);
    float ni = 1.0f / fmaxf(sqrtf(ss), 1e-12f);
    float4 o = make_float4(acc.x * ni, acc.y * ni, acc.z * ni, acc.w * ni);
    if (cur_out) ((uint2*)(cur_out + (size_t)gw * C))[lane] = pack4(o.x, o.y, o.z, o.w);
    if (res) {
        float4 pv = unpack4(__ldg((const uint2*)(prev + (size_t)gw * C) + lane));
        float4 r = __ldg((const float4*)(res_init + (size_t)gw * C) + lane);
        r.x += pv.x + o.x; r.y += pv.y + o.y; r.z += pv.z + o.z; r.w += pv.w + o.w;
        ((float4*)(res + (size_t)gw * C))[lane] = r;
    }
}

// ================= host launcher =================
extern "C" void kernel_launch(void* const* d_in, const int* in_sizes, int n_in,
                              void* d_out, int out_size)
{
    const float* user   = (const float*)d_in[0];
    const float* ent    = (const float*)d_in[1];
    const int*   eidx   = (const int*)  d_in[2];
    const int*   etype  = (const int*)  d_in[3];
    const int*   exidx  = (const int*)  d_in[4];
    const int*   irows  = (const int*)  d_in[6];
    const int*   icols  = (const int*)  d_in[7];
    const float* ivals  = (const float*)d_in[8];
    const float* weight = (const float*)d_in[9];
    const float* WQ     = (const float*)d_in[11];
    const float* WK     = (const float*)d_in[12];

    int n_users = in_sizes[0] / C;
    int n_ent   = in_sizes[1] / C;
    int n_nodes = n_users + n_ent;
    int E   = in_sizes[3];
    int EX  = in_sizes[5];
    int NNZ = in_sizes[6];

    size_t UB = (size_t)n_users * C;
    size_t EB = (size_t)n_ent * C;

    float *augp;
    __half *hNodeA, *hNodeB, *hEntB, *hEntM, *hEntM2, *hUserB, *hQ, *hK, *WT;
    float2* exps;
    int *srt_e, *srt_x, *off3, *cur3, *deg3, *part3;
    int2* srt_i;
    cudaGetSymbolAddress((void**)&hNodeA, g_hNodeA);
    cudaGetSymbolAddress((void**)&hNodeB, g_hNodeB);
    cudaGetSymbolAddress((void**)&hEntB,  g_hEntB);
    cudaGetSymbolAddress((void**)&hEntM,  g_hEntM);
    cudaGetSymbolAddress((void**)&hEntM2, g_hEntM2);
    cudaGetSymbolAddress((void**)&hUserB, g_hUserB);
    cudaGetSymbolAddress((void**)&hQ,     g_hQ);
    cudaGetSymbolAddress((void**)&hK,     g_hK);
    cudaGetSymbolAddress((void**)&WT,     g_WT);
    cudaGetSymbolAddress((void**)&augp,   g_aug);
    cudaGetSymbolAddress((void**)&exps,   g_exps);
    cudaGetSymbolAddress((void**)&srt_e,  g_srt_ent);
    cudaGetSymbolAddress((void**)&srt_x,  g_srt_x);
    cudaGetSymbolAddress((void**)&srt_i,  g_srt_i);
    cudaGetSymbolAddress((void**)&off3,   g_off3);
    cudaGetSymbolAddress((void**)&cur3,   g_cur3);
    cudaGetSymbolAddress((void**)&deg3,   g_deg3);
    cudaGetSymbolAddress((void**)&part3,  g_part3);

    int* off_e = off3;
    int* off_n = off3 + OFFS;
    int* off_u = off3 + 2 * OFFS;

    float* out = (float*)d_out;
    float* user_res = out;              // [n_users, C]
    float* ent_res  = out + UB;         // [n_ent, C]
    float* node_res = out + UB + EB;    // [n_nodes, C]

    const int* eh = eidx;          const int* et = eidx + E;
    const int* xh = exidx;         const int* xt = exidx + EX;

    // ---- fork from origin stream FIRST (required for graph capture) ----
    cudaEventRecord(g_hx.evFork, 0);
    cudaStreamWaitEvent(g_hx.sA, g_hx.evFork, 0);
    cudaStreamWaitEvent(g_hx.sB, g_hx.evFork, 0);

    // ---- stream B: full CSR build (depends only on edge lists) ----
    zero_deg3<<<(3 * DEGS + 255) / 256, 256, 0, g_hx.sB>>>(deg3);
    {
        int tot = E + EX + NNZ;
        hist3<<<(tot + 255) / 256, 256, 0, g_hx.sB>>>(eh, E, xh, EX, irows, NNZ, deg3);
    }
    {
        dim3 g((n_nodes + 1023) >> 10, 3);
        scan_block3<<<g, 1024, 0, g_hx.sB>>>(deg3, off3, part3, n_ent, n_nodes, n_users);
        scan_part3<<<1, 96, 0, g_hx.sB>>>(part3);
        dim3 g2((n_nodes + 256) / 256 + 1, 3);
        add_offs3<<<g2, 256, 0, g_hx.sB>>>(off3, cur3, part3, n_ent, n_nodes, n_users);
    }
    {
        int tot = E + EX + NNZ;
        scat3<<<(tot + 255) / 256, 256, 0, g_hx.sB>>>(eh, et, etype, E, xh, xt, EX,
                                                      irows, icols, ivals, NNZ,
                                                      cur3, srt_e, srt_x, srt_i);
    }
    cudaEventRecord(g_hx.evCSR, g_hx.sB);

    // ---- main: fp16 concat of node embeddings ----
    {
        size_t n4 = (size_t)n_nodes * 32;
        conv2<<<(unsigned)((n4 + 255) / 256), 256>>>(user, ent, UB / 4, n4, hNodeA);
    }
    cudaEventRecord(g_hx.evConv, 0);

    // ---- stream A: wt_conv -> qk_mma -> fused attn+node1 -> node2 ----
    wt_conv<<<(2 * C * C + 255) / 256, 256, 0, g_hx.sA>>>(WQ, WK, WT);
    cudaStreamWaitEvent(g_hx.sA, g_hx.evConv, 0);
    {
        int smem = (SB_H + SA_H) * 2;
        cudaFuncSetAttribute(qk_mma, cudaFuncAttributeMaxDynamicSharedMemorySize, smem);
        qk_mma<<<(n_nodes + 63) / 64, 256, smem, g_hx.sA>>>(hNodeA, WT, hQ, hK, n_nodes);
    }
    cudaStreamWaitEvent(g_hx.sA, g_hx.evCSR, 0);

    int gbN = (n_nodes * 32 + 255) / 256;
    int gbE = (n_ent   * 32 + 255) / 256;
    int gbU = (n_users * 32 + 255) / 256;

    attn_node1_csr<<<gbN, 256, 0, g_hx.sA>>>(
        off_n, srt_x, hQ, hK, hNodeA, exps, augp, hNodeB, n_nodes);
    node_agg_csr<<<gbN, 256, 0, g_hx.sA>>>(
        off_n, srt_x, augp, hNodeB, node_res,
        user, ent, n_users, hNodeB, n_nodes);
    cudaEventRecord(g_hx.evA, g_hx.sA);

    // ---- main: ent1 (needs conv2 [main order] + CSR) ----
    cudaStreamWaitEvent(0, g_hx.evCSR, 0);
    ent_agg_csr<<<gbE, 256>>>(
        off_e, srt_e, hNodeA + UB, weight, hEntM, hEntB,
        (float*)0, (const float*)0, (const __half*)0, n_ent);
    cudaEventRecord(g_hx.evE1, 0);

    // ---- stream B: user1 (needs entM1) ----
    cudaStreamWaitEvent(g_hx.sB, g_hx.evE1, 0);
    user_agg_csr<<<gbU, 256, 0, g_hx.sB>>>(
        off_u, srt_i, hEntM, hUserB, (float*)0, (const float*)0,
        (const __half*)0, n_users);
    cudaEventRecord(g_hx.evB, g_hx.sB);

    // ---- main: ent2 (writes ent_res) ----
    ent_agg_csr<<<gbE, 256>>>(
        off_e, srt_e, hEntB, weight, hEntM2, (__half*)0,
        ent_res, ent, hEntB, n_ent);

    // ---- main: user2 (needs entM2 [main-ordered] + userB [evB]) ----
    cudaStreamWaitEvent(0, g_hx.evB, 0);
    user_agg_csr<<<gbU, 256>>>(
        off_u, srt_i, hEntM2, (__half*)0, user_res, user, hUserB, n_users);

    // ---- join stream A ----
    cudaStreamWaitEvent(0, g_hx.evA, 0);
}